// round 1
// baseline (speedup 1.0000x reference)
#include <cuda_runtime.h>
#include <cuda_bf16.h>

// Problem constants
#define T_CTX 2048
#define D_MODEL 2048
#define N_Q 32
#define N_KV 8
#define HEAD_DIM 64
#define KV_DIM (N_KV * HEAD_DIM)   // 512

// Scratch (allocation-free rule: __device__ globals)
__device__ float g_q[T_CTX * D_MODEL];     // [T, 32, 64]
__device__ float g_k[T_CTX * KV_DIM];      // [T, 8, 64]
__device__ float g_v[T_CTX * KV_DIM];      // [T, 8, 64]
__device__ float g_attn[T_CTX * D_MODEL];  // [T, 32, 64]

// ---------------------------------------------------------------------------
// SGEMM: C[M,N] = A[M,K] @ B[K,N] + bias[N]
// 128x128 block tile, BK=8, 256 threads, 8x8 per-thread microtile, float4 IO.
// Requires M%128==0, N%128==0, K%8==0 (true for all uses here).
// ---------------------------------------------------------------------------
#define BM 128
#define BN 128
#define BK 8
#define TM 8
#define TN 8

__global__ __launch_bounds__(256) void sgemm_bias_kernel(
    const float* __restrict__ A, const float* __restrict__ B,
    const float* __restrict__ bias, float* __restrict__ C,
    int M, int N, int K)
{
    __shared__ float As[BK][BM];
    __shared__ float Bs[BK][BN];

    const int tid  = threadIdx.x;
    const int brow = blockIdx.y;
    const int bcol = blockIdx.x;

    // A tile load mapping: 128 rows x 8 cols -> 256 float4 loads
    const int arow  = tid >> 1;          // 0..127
    const int acol4 = (tid & 1) * 4;     // 0 or 4
    // B tile load mapping: 8 rows x 128 cols -> 256 float4 loads
    const int browi = tid >> 5;          // 0..7
    const int bcol4 = (tid & 31) * 4;    // 0..124

    const int trow = (tid >> 4) * TM;    // 0..120
    const int tcol = (tid & 15) * TN;    // 0..120

    const float* Ab = A + (size_t)brow * BM * K;
    const float* Bb = B + (size_t)bcol * BN;

    float acc[TM][TN];
#pragma unroll
    for (int i = 0; i < TM; ++i)
#pragma unroll
        for (int j = 0; j < TN; ++j) acc[i][j] = 0.f;

    for (int k0 = 0; k0 < K; k0 += BK) {
        float4 av = *(const float4*)(Ab + (size_t)arow * K + k0 + acol4);
        As[acol4 + 0][arow] = av.x;
        As[acol4 + 1][arow] = av.y;
        As[acol4 + 2][arow] = av.z;
        As[acol4 + 3][arow] = av.w;
        *(float4*)&Bs[browi][bcol4] =
            *(const float4*)(Bb + (size_t)(k0 + browi) * N + bcol4);
        __syncthreads();

#pragma unroll
        for (int k = 0; k < BK; ++k) {
            float ra[TM], rb[TN];
#pragma unroll
            for (int i = 0; i < TM; ++i) ra[i] = As[k][trow + i];
#pragma unroll
            for (int j = 0; j < TN; ++j) rb[j] = Bs[k][tcol + j];
#pragma unroll
            for (int i = 0; i < TM; ++i)
#pragma unroll
                for (int j = 0; j < TN; ++j)
                    acc[i][j] += ra[i] * rb[j];
        }
        __syncthreads();
    }

    // Epilogue with bias
    const int gcol0 = bcol * BN + tcol;
    const int grow0 = brow * BM + trow;
#pragma unroll
    for (int i = 0; i < TM; ++i) {
        float* crow = C + (size_t)(grow0 + i) * N + gcol0;
#pragma unroll
        for (int j4 = 0; j4 < TN; j4 += 4) {
            float4 o;
            o.x = acc[i][j4 + 0] + bias[gcol0 + j4 + 0];
            o.y = acc[i][j4 + 1] + bias[gcol0 + j4 + 1];
            o.z = acc[i][j4 + 2] + bias[gcol0 + j4 + 2];
            o.w = acc[i][j4 + 3] + bias[gcol0 + j4 + 3];
            *(float4*)(crow + j4) = o;
        }
    }
}

// ---------------------------------------------------------------------------
// RoPE: in-place on [T, nheads, 64]; freqs is [T, 32]
// out[i]    = x[i]*cos - x[i+32]*sin
// out[i+32] = x[i]*sin + x[i+32]*cos
// ---------------------------------------------------------------------------
__global__ void rope_kernel(float* __restrict__ x, const float* __restrict__ freqs,
                            int nheads, int total)
{
    int idx = blockIdx.x * blockDim.x + threadIdx.x;
    if (idx >= total) return;
    int i = idx & 31;
    int h = (idx >> 5) % nheads;
    int t = idx / (32 * nheads);
    float f = freqs[t * 32 + i];
    float c = cosf(f), s = sinf(f);
    float* base = x + ((size_t)t * nheads + h) * HEAD_DIM;
    float x1 = base[i];
    float x2 = base[i + 32];
    base[i]      = x1 * c - x2 * s;
    base[i + 32] = x1 * s + x2 * c;
}

// ---------------------------------------------------------------------------
// Flash attention (causal, GQA). One CTA per (head, 64-query tile).
// 256 threads; each owns a 4x4 patch of the 64x64 O tile.
// Dynamic smem layout:
//   Qs  [64*64]
//   KVs [64*65]  (padded; K then V sequenced by barriers)
//   Ss  [64*64]  (scores -> probabilities)
//   m_s[64], l_s[64], resc[64]
// ---------------------------------------------------------------------------
#define ATTN_SMEM_FLOATS (64*64 + 64*65 + 64*64 + 3*64)
#define ATTN_SMEM_BYTES  (ATTN_SMEM_FLOATS * 4)

__global__ __launch_bounds__(256) void attn_kernel(
    const float* __restrict__ Q, const float* __restrict__ K,
    const float* __restrict__ V, float* __restrict__ O)
{
    extern __shared__ float sm[];
    float* Qs  = sm;                  // 4096
    float* KVs = Qs + 64 * 64;        // 4160 (stride 65)
    float* Ss  = KVs + 64 * 65;       // 4096
    float* m_s  = Ss + 64 * 64;
    float* l_s  = m_s + 64;
    float* resc = l_s + 64;

    const int h   = blockIdx.x;       // 0..31
    const int qt  = blockIdx.y;       // 0..31
    const int kvh = h >> 2;           // GQA: 4 Q heads per KV head
    const int tid = threadIdx.x;
    const int tx  = tid & 15;
    const int ty  = tid >> 4;
    const int r0  = ty * 4;
    const int c0  = tx * 4;
    const float scale = 0.125f;       // 1/sqrt(64)

    // Load Q tile (64x64), coalesced float4
    for (int i = tid; i < 64 * 16; i += 256) {
        int r = i >> 4, d4 = (i & 15) * 4;
        *(float4*)(Qs + r * 64 + d4) =
            *(const float4*)(Q + (size_t)(qt * 64 + r) * D_MODEL + h * HEAD_DIM + d4);
    }
    if (tid < 64) { m_s[tid] = -1e30f; l_s[tid] = 0.f; }

    float acc[4][4];
#pragma unroll
    for (int i = 0; i < 4; ++i)
#pragma unroll
        for (int j = 0; j < 4; ++j) acc[i][j] = 0.f;

    for (int kt = 0; kt <= qt; ++kt) {
        __syncthreads();  // prior PV reads of KVs / init complete
        // Load K tile into KVs (padded stride 65)
        for (int i = tid; i < 64 * 16; i += 256) {
            int r = i >> 4, d4 = (i & 15) * 4;
            float4 kv = *(const float4*)(K + (size_t)(kt * 64 + r) * KV_DIM + kvh * HEAD_DIM + d4);
            KVs[r * 65 + d4 + 0] = kv.x;
            KVs[r * 65 + d4 + 1] = kv.y;
            KVs[r * 65 + d4 + 2] = kv.z;
            KVs[r * 65 + d4 + 3] = kv.w;
        }
        __syncthreads();

        // S = scale * Q @ K^T (masked on diagonal tile)
        float s[4][4];
#pragma unroll
        for (int i = 0; i < 4; ++i)
#pragma unroll
            for (int j = 0; j < 4; ++j) s[i][j] = 0.f;

#pragma unroll 8
        for (int d = 0; d < 64; ++d) {
            float qr[4], kc[4];
#pragma unroll
            for (int i = 0; i < 4; ++i) qr[i] = Qs[(r0 + i) * 64 + d];
#pragma unroll
            for (int j = 0; j < 4; ++j) kc[j] = KVs[(c0 + j) * 65 + d];
#pragma unroll
            for (int i = 0; i < 4; ++i)
#pragma unroll
                for (int j = 0; j < 4; ++j)
                    s[i][j] += qr[i] * kc[j];
        }
        const bool diag = (kt == qt);
#pragma unroll
        for (int i = 0; i < 4; ++i)
#pragma unroll
            for (int j = 0; j < 4; ++j) {
                float val = s[i][j] * scale;
                if (diag && (c0 + j) > (r0 + i)) val = -1e30f;
                Ss[(r0 + i) * 64 + c0 + j] = val;
            }
        __syncthreads();

        // Online softmax row update (64 rows, one thread each)
        if (tid < 64) {
            const int r = tid;
            float m_old = m_s[r];
            float mmax = m_old;
#pragma unroll 8
            for (int c = 0; c < 64; ++c) mmax = fmaxf(mmax, Ss[r * 64 + c]);
            float rf = __expf(m_old - mmax);
            float lsum = l_s[r] * rf;
#pragma unroll 8
            for (int c = 0; c < 64; ++c) {
                float p = __expf(Ss[r * 64 + c] - mmax);
                Ss[r * 64 + c] = p;
                lsum += p;
            }
            m_s[r] = mmax; l_s[r] = lsum; resc[r] = rf;
        }
        __syncthreads();

        // Load V tile into KVs (reuses K buffer)
        for (int i = tid; i < 64 * 16; i += 256) {
            int r = i >> 4, d4 = (i & 15) * 4;
            float4 vv = *(const float4*)(V + (size_t)(kt * 64 + r) * KV_DIM + kvh * HEAD_DIM + d4);
            KVs[r * 65 + d4 + 0] = vv.x;
            KVs[r * 65 + d4 + 1] = vv.y;
            KVs[r * 65 + d4 + 2] = vv.z;
            KVs[r * 65 + d4 + 3] = vv.w;
        }
        __syncthreads();

        // O = O * resc + P @ V
        float rs[4];
#pragma unroll
        for (int i = 0; i < 4; ++i) rs[i] = resc[r0 + i];
#pragma unroll
        for (int i = 0; i < 4; ++i)
#pragma unroll
            for (int j = 0; j < 4; ++j) acc[i][j] *= rs[i];

#pragma unroll 8
        for (int ks = 0; ks < 64; ++ks) {
            float p[4], vv[4];
#pragma unroll
            for (int i = 0; i < 4; ++i) p[i] = Ss[(r0 + i) * 64 + ks];
#pragma unroll
            for (int j = 0; j < 4; ++j) vv[j] = KVs[ks * 65 + c0 + j];
#pragma unroll
            for (int i = 0; i < 4; ++i)
#pragma unroll
                for (int j = 0; j < 4; ++j)
                    acc[i][j] += p[i] * vv[j];
        }
    }
    __syncthreads();

    // Epilogue: normalize and write [T, 32*64]
    float linv[4];
#pragma unroll
    for (int i = 0; i < 4; ++i) linv[i] = 1.f / l_s[r0 + i];
#pragma unroll
    for (int i = 0; i < 4; ++i)
#pragma unroll
        for (int j = 0; j < 4; ++j)
            O[(size_t)(qt * 64 + r0 + i) * D_MODEL + h * HEAD_DIM + c0 + j] =
                acc[i][j] * linv[i];
}

// ---------------------------------------------------------------------------
// Launch
// ---------------------------------------------------------------------------
extern "C" void kernel_launch(void* const* d_in, const int* in_sizes, int n_in,
                              void* d_out, int out_size)
{
    const float* x     = (const float*)d_in[0];
    const float* Wq    = (const float*)d_in[1];
    const float* bq    = (const float*)d_in[2];
    const float* Wk    = (const float*)d_in[3];
    const float* bk    = (const float*)d_in[4];
    const float* Wv    = (const float*)d_in[5];
    const float* bv    = (const float*)d_in[6];
    const float* Wo    = (const float*)d_in[7];
    const float* bo    = (const float*)d_in[8];
    const float* freqs = (const float*)d_in[9];
    float* out = (float*)d_out;

    float *qp, *kp, *vp, *ap;
    cudaGetSymbolAddress((void**)&qp, g_q);
    cudaGetSymbolAddress((void**)&kp, g_k);
    cudaGetSymbolAddress((void**)&vp, g_v);
    cudaGetSymbolAddress((void**)&ap, g_attn);

    cudaFuncSetAttribute(attn_kernel, cudaFuncAttributeMaxDynamicSharedMemorySize,
                         ATTN_SMEM_BYTES);

    dim3 gq(D_MODEL / BN, T_CTX / BM);   // (16,16)
    dim3 gkv(KV_DIM / BN, T_CTX / BM);   // (4,16)

    sgemm_bias_kernel<<<gq, 256>>>(x, Wq, bq, qp, T_CTX, D_MODEL, D_MODEL);
    sgemm_bias_kernel<<<gkv, 256>>>(x, Wk, bk, kp, T_CTX, KV_DIM, D_MODEL);
    sgemm_bias_kernel<<<gkv, 256>>>(x, Wv, bv, vp, T_CTX, KV_DIM, D_MODEL);

    int tq = T_CTX * N_Q * 32;
    int tk = T_CTX * N_KV * 32;
    rope_kernel<<<(tq + 255) / 256, 256>>>(qp, freqs, N_Q, tq);
    rope_kernel<<<(tk + 255) / 256, 256>>>(kp, freqs, N_KV, tk);

    attn_kernel<<<dim3(N_Q, T_CTX / 64), 256, ATTN_SMEM_BYTES>>>(qp, kp, vp, ap);

    sgemm_bias_kernel<<<gq, 256>>>(ap, Wo, bo, out, T_CTX, D_MODEL, D_MODEL);
}

// round 3
// speedup vs baseline: 1.7600x; 1.7600x over previous
#include <cuda_runtime.h>
#include <cuda_bf16.h>
#include <cstdint>

// Problem constants
#define T_CTX 2048
#define D_MODEL 2048
#define N_Q 32
#define N_KV 8
#define HEAD_DIM 64
#define KV_DIM (N_KV * HEAD_DIM)   // 512

// ---------------------------------------------------------------------------
// Scratch (allocation-free rule: __device__ globals)
// ---------------------------------------------------------------------------
__device__ __align__(16) float g_q[T_CTX * D_MODEL];
__device__ __align__(16) float g_k[T_CTX * KV_DIM];
__device__ __align__(16) float g_v[T_CTX * KV_DIM];
__device__ __align__(16) float g_attn[T_CTX * D_MODEL];
__device__ __align__(16) __nv_bfloat16 s_ahi[T_CTX * D_MODEL];
__device__ __align__(16) __nv_bfloat16 s_alo[T_CTX * D_MODEL];
__device__ __align__(16) __nv_bfloat16 s_bhi[D_MODEL * D_MODEL];  // W^T [N,K]
__device__ __align__(16) __nv_bfloat16 s_blo[D_MODEL * D_MODEL];

// ---------------------------------------------------------------------------
// PTX helpers
// ---------------------------------------------------------------------------
__device__ __forceinline__ uint32_t smem_u32(const void* p) {
    uint32_t a;
    asm("{ .reg .u64 t; cvta.to.shared.u64 t, %1; cvt.u32.u64 %0, t; }"
        : "=r"(a) : "l"(p));
    return a;
}

__device__ __forceinline__ void cp_async16(uint32_t dst, const void* src) {
    asm volatile("cp.async.ca.shared.global [%0], [%1], 16;"
                 :: "r"(dst), "l"(src) : "memory");
}
#define CP_COMMIT() asm volatile("cp.async.commit_group;" ::: "memory")
#define CP_WAIT(n)  asm volatile("cp.async.wait_group %0;" :: "n"(n) : "memory")

__device__ __forceinline__ void ldsm_x4(uint32_t (&r)[4], uint32_t addr) {
    asm volatile("ldmatrix.sync.aligned.m8n8.x4.shared.b16 {%0,%1,%2,%3}, [%4];"
                 : "=r"(r[0]), "=r"(r[1]), "=r"(r[2]), "=r"(r[3]) : "r"(addr));
}

__device__ __forceinline__ void mma16816(float (&d)[4], const uint32_t (&a)[4],
                                         uint32_t b0, uint32_t b1) {
    asm volatile(
        "mma.sync.aligned.m16n8k16.row.col.f32.bf16.bf16.f32 "
        "{%0,%1,%2,%3}, {%4,%5,%6,%7}, {%8,%9}, {%0,%1,%2,%3};"
        : "+f"(d[0]), "+f"(d[1]), "+f"(d[2]), "+f"(d[3])
        : "r"(a[0]), "r"(a[1]), "r"(a[2]), "r"(a[3]), "r"(b0), "r"(b1));
}

// smem tile layout: 128 rows x 32 bf16 (64B row, four 16B chunks).
// swizzle: chunk' = chunk ^ ((row>>1)&3) -> conflict-free ldmatrix phases.
__device__ __forceinline__ uint32_t toff(int r, int c) {
    return (uint32_t)((r << 6) + ((c ^ ((r >> 1) & 3)) << 4));
}

// ---------------------------------------------------------------------------
// bf16-split tensor-core GEMM: C[M,N] = (Ah+Al)[M,K] @ ((Bh+Bl)[N,K])^T + bias
// BM=BN=128, BK=32, 256 threads (8 warps as 2x4), warp tile 64x32.
// ---------------------------------------------------------------------------
#define GEMM_SMEM_BYTES (2 * 4 * 8192)   // 2 stages x 4 tiles x 8KB = 64KB

__device__ __forceinline__ void stage_load(
    uint32_t stage_base,
    const __nv_bfloat16* __restrict__ Ah, const __nv_bfloat16* __restrict__ Al,
    const __nv_bfloat16* __restrict__ Bh, const __nv_bfloat16* __restrict__ Bl,
    int arow0, int brow0, int k0, int K, int tid)
{
    const __nv_bfloat16* srcs[4] = {Ah, Al, Bh, Bl};
#pragma unroll
    for (int t = 0; t < 4; ++t) {
        const __nv_bfloat16* src = srcs[t];
        const int grow0 = (t < 2) ? arow0 : brow0;
        const uint32_t tb = stage_base + t * 8192;
#pragma unroll
        for (int j = 0; j < 2; ++j) {
            const int idx = j * 256 + tid;      // 0..511
            const int r = idx >> 2;             // 0..127
            const int c = idx & 3;              // chunk
            cp_async16(tb + toff(r, c),
                       src + (size_t)(grow0 + r) * K + k0 + c * 8);
        }
    }
}

__global__ __launch_bounds__(256, 1) void gemm_tc_kernel(
    const __nv_bfloat16* __restrict__ Ahi, const __nv_bfloat16* __restrict__ Alo,
    const __nv_bfloat16* __restrict__ Bhi, const __nv_bfloat16* __restrict__ Blo,
    const float* __restrict__ bias, float* __restrict__ C,
    int M, int N, int K)
{
    extern __shared__ __align__(1024) char smem_raw[];
    const uint32_t sb = smem_u32(smem_raw);

    const int tid = threadIdx.x;
    const int wid = tid >> 5;
    const int lid = tid & 31;
    const int wm = wid & 1;          // 0..1
    const int wn = wid >> 1;         // 0..3
    const int arow0 = blockIdx.y * 128;
    const int brow0 = blockIdx.x * 128;

    float acc[4][4][4];
#pragma unroll
    for (int i = 0; i < 4; ++i)
#pragma unroll
        for (int j = 0; j < 4; ++j)
#pragma unroll
            for (int q = 0; q < 4; ++q) acc[i][j][q] = 0.f;

    const int NT = K >> 5;  // BK=32

    stage_load(sb, Ahi, Alo, Bhi, Blo, arow0, brow0, 0, K, tid);
    CP_COMMIT();
    stage_load(sb + 32768, Ahi, Alo, Bhi, Blo, arow0, brow0, 32, K, tid);
    CP_COMMIT();

    // precomputed ldmatrix lane offsets (within a tile)
    const int sub = lid >> 3;
    const int l7  = lid & 7;
    // A-frag: row = base + (sub&1)*8 + l7, chunk = kc + (sub>>1)
    const int a_rofs = ((sub & 1) << 3) + l7;
    const int a_cofs = (sub >> 1);
    // B-frag: row = base + (sub>>1)*8 + l7, chunk = kc + (sub&1)
    const int b_rofs = ((sub >> 1) << 3) + l7;
    const int b_cofs = (sub & 1);

    for (int kt = 0; kt < NT; ++kt) {
        if (kt == NT - 1) { CP_WAIT(0); } else { CP_WAIT(1); }
        __syncthreads();

        const uint32_t st = sb + (kt & 1) * 32768;
        const uint32_t tAh = st, tAl = st + 8192, tBh = st + 16384, tBl = st + 24576;

#pragma unroll
        for (int ks = 0; ks < 2; ++ks) {
            const int kc = ks * 2;
            uint32_t ah[4][4], al[4][4];
#pragma unroll
            for (int ma = 0; ma < 4; ++ma) {
                const int row = wm * 64 + ma * 16 + a_rofs;
                const uint32_t o = toff(row, kc + a_cofs);
                ldsm_x4(ah[ma], tAh + o);
                ldsm_x4(al[ma], tAl + o);
            }
            uint32_t bh[2][4], bl[2][4];
#pragma unroll
            for (int nb = 0; nb < 2; ++nb) {
                const int row = wn * 32 + nb * 16 + b_rofs;
                const uint32_t o = toff(row, kc + b_cofs);
                ldsm_x4(bh[nb], tBh + o);
                ldsm_x4(bl[nb], tBl + o);
            }
#pragma unroll
            for (int ma = 0; ma < 4; ++ma) {
#pragma unroll
                for (int na = 0; na < 4; ++na) {
                    const int nb = na >> 1;
                    const int hi2 = (na & 1) << 1;
                    mma16816(acc[ma][na], ah[ma], bh[nb][hi2], bh[nb][hi2 + 1]);
                    mma16816(acc[ma][na], ah[ma], bl[nb][hi2], bl[nb][hi2 + 1]);
                    mma16816(acc[ma][na], al[ma], bh[nb][hi2], bh[nb][hi2 + 1]);
                }
            }
        }
        __syncthreads();

        if (kt + 2 < NT) {
            stage_load(st, Ahi, Alo, Bhi, Blo, arow0, brow0, (kt + 2) << 5, K, tid);
            CP_COMMIT();
        }
    }

    // Epilogue: c-frag thread mapping: rows t/4, t/4+8; cols (t%4)*2, +1
    const int er = lid >> 2;
    const int ec = (lid & 3) << 1;
#pragma unroll
    for (int ma = 0; ma < 4; ++ma) {
        const int row = arow0 + wm * 64 + ma * 16 + er;
#pragma unroll
        for (int na = 0; na < 4; ++na) {
            const int col = brow0 + wn * 32 + na * 8 + ec;
            const float b0 = bias[col], b1 = bias[col + 1];
            float2 v0 = make_float2(acc[ma][na][0] + b0, acc[ma][na][1] + b1);
            float2 v1 = make_float2(acc[ma][na][2] + b0, acc[ma][na][3] + b1);
            *(float2*)(C + (size_t)row * N + col) = v0;
            *(float2*)(C + (size_t)(row + 8) * N + col) = v1;
        }
    }
}

// ---------------------------------------------------------------------------
// fp32 -> bf16 hi/lo split, elementwise (vectorized)
// ---------------------------------------------------------------------------
__global__ void cvt_hilo_kernel(const float* __restrict__ in,
                                __nv_bfloat16* __restrict__ hi,
                                __nv_bfloat16* __restrict__ lo, int n4)
{
    int i = blockIdx.x * blockDim.x + threadIdx.x;
    if (i >= n4) return;
    float4 v = ((const float4*)in)[i];
    __nv_bfloat16 h0 = __float2bfloat16(v.x);
    __nv_bfloat16 h1 = __float2bfloat16(v.y);
    __nv_bfloat16 h2 = __float2bfloat16(v.z);
    __nv_bfloat16 h3 = __float2bfloat16(v.w);
    __nv_bfloat16 l0 = __float2bfloat16(v.x - __bfloat162float(h0));
    __nv_bfloat16 l1 = __float2bfloat16(v.y - __bfloat162float(h1));
    __nv_bfloat16 l2 = __float2bfloat16(v.z - __bfloat162float(h2));
    __nv_bfloat16 l3 = __float2bfloat16(v.w - __bfloat162float(h3));
    uint2 ph, pl;
    ph.x = ((uint32_t)__bfloat16_as_ushort(h1) << 16) | __bfloat16_as_ushort(h0);
    ph.y = ((uint32_t)__bfloat16_as_ushort(h3) << 16) | __bfloat16_as_ushort(h2);
    pl.x = ((uint32_t)__bfloat16_as_ushort(l1) << 16) | __bfloat16_as_ushort(l0);
    pl.y = ((uint32_t)__bfloat16_as_ushort(l3) << 16) | __bfloat16_as_ushort(l2);
    ((uint2*)hi)[i] = ph;
    ((uint2*)lo)[i] = pl;
}

// ---------------------------------------------------------------------------
// Weight transpose + split: W[K,N] fp32 -> hi/lo bf16 [N,K]
// ---------------------------------------------------------------------------
__global__ __launch_bounds__(256) void cvtT_kernel(
    const float* __restrict__ W, __nv_bfloat16* __restrict__ hi,
    __nv_bfloat16* __restrict__ lo, int K, int N)
{
    __shared__ float t[32][33];
    const int nb = blockIdx.x * 32, kb = blockIdx.y * 32;
    const int tx = threadIdx.x & 31, ty = threadIdx.x >> 5;
#pragma unroll
    for (int i = 0; i < 32; i += 8)
        t[ty + i][tx] = W[(size_t)(kb + ty + i) * N + nb + tx];
    __syncthreads();
#pragma unroll
    for (int i = 0; i < 32; i += 8) {
        const int n = nb + ty + i, k = kb + tx;
        const float v = t[tx][ty + i];
        const __nv_bfloat16 h = __float2bfloat16(v);
        hi[(size_t)n * K + k] = h;
        lo[(size_t)n * K + k] = __float2bfloat16(v - __bfloat162float(h));
    }
}

// ---------------------------------------------------------------------------
// RoPE
// ---------------------------------------------------------------------------
__global__ void rope_kernel(float* __restrict__ x, const float* __restrict__ freqs,
                            int nheads, int total)
{
    int idx = blockIdx.x * blockDim.x + threadIdx.x;
    if (idx >= total) return;
    int i = idx & 31;
    int h = (idx >> 5) % nheads;
    int t = idx / (32 * nheads);
    float f = freqs[t * 32 + i];
    float c = cosf(f), s = sinf(f);
    float* base = x + ((size_t)t * nheads + h) * HEAD_DIM;
    float x1 = base[i];
    float x2 = base[i + 32];
    base[i]      = x1 * c - x2 * s;
    base[i + 32] = x1 * s + x2 * c;
}

// ---------------------------------------------------------------------------
// Flash attention (causal, GQA) — scalar version (unchanged)
// ---------------------------------------------------------------------------
#define ATTN_SMEM_FLOATS (64*64 + 64*65 + 64*64 + 3*64)
#define ATTN_SMEM_BYTES  (ATTN_SMEM_FLOATS * 4)

__global__ __launch_bounds__(256) void attn_kernel(
    const float* __restrict__ Q, const float* __restrict__ K,
    const float* __restrict__ V, float* __restrict__ O)
{
    extern __shared__ float sm[];
    float* Qs  = sm;
    float* KVs = Qs + 64 * 64;
    float* Ss  = KVs + 64 * 65;
    float* m_s  = Ss + 64 * 64;
    float* l_s  = m_s + 64;
    float* resc = l_s + 64;

    const int h   = blockIdx.x;
    const int qt  = blockIdx.y;
    const int kvh = h >> 2;
    const int tid = threadIdx.x;
    const int tx  = tid & 15;
    const int ty  = tid >> 4;
    const int r0  = ty * 4;
    const int c0  = tx * 4;
    const float scale = 0.125f;

    for (int i = tid; i < 64 * 16; i += 256) {
        int r = i >> 4, d4 = (i & 15) * 4;
        *(float4*)(Qs + r * 64 + d4) =
            *(const float4*)(Q + (size_t)(qt * 64 + r) * D_MODEL + h * HEAD_DIM + d4);
    }
    if (tid < 64) { m_s[tid] = -1e30f; l_s[tid] = 0.f; }

    float acc[4][4];
#pragma unroll
    for (int i = 0; i < 4; ++i)
#pragma unroll
        for (int j = 0; j < 4; ++j) acc[i][j] = 0.f;

    for (int kt = 0; kt <= qt; ++kt) {
        __syncthreads();
        for (int i = tid; i < 64 * 16; i += 256) {
            int r = i >> 4, d4 = (i & 15) * 4;
            float4 kv = *(const float4*)(K + (size_t)(kt * 64 + r) * KV_DIM + kvh * HEAD_DIM + d4);
            KVs[r * 65 + d4 + 0] = kv.x;
            KVs[r * 65 + d4 + 1] = kv.y;
            KVs[r * 65 + d4 + 2] = kv.z;
            KVs[r * 65 + d4 + 3] = kv.w;
        }
        __syncthreads();

        float s[4][4];
#pragma unroll
        for (int i = 0; i < 4; ++i)
#pragma unroll
            for (int j = 0; j < 4; ++j) s[i][j] = 0.f;

#pragma unroll 8
        for (int d = 0; d < 64; ++d) {
            float qr[4], kc[4];
#pragma unroll
            for (int i = 0; i < 4; ++i) qr[i] = Qs[(r0 + i) * 64 + d];
#pragma unroll
            for (int j = 0; j < 4; ++j) kc[j] = KVs[(c0 + j) * 65 + d];
#pragma unroll
            for (int i = 0; i < 4; ++i)
#pragma unroll
                for (int j = 0; j < 4; ++j)
                    s[i][j] += qr[i] * kc[j];
        }
        const bool diag = (kt == qt);
#pragma unroll
        for (int i = 0; i < 4; ++i)
#pragma unroll
            for (int j = 0; j < 4; ++j) {
                float val = s[i][j] * scale;
                if (diag && (c0 + j) > (r0 + i)) val = -1e30f;
                Ss[(r0 + i) * 64 + c0 + j] = val;
            }
        __syncthreads();

        if (tid < 64) {
            const int r = tid;
            float m_old = m_s[r];
            float mmax = m_old;
#pragma unroll 8
            for (int c = 0; c < 64; ++c) mmax = fmaxf(mmax, Ss[r * 64 + c]);
            float rf = __expf(m_old - mmax);
            float lsum = l_s[r] * rf;
#pragma unroll 8
            for (int c = 0; c < 64; ++c) {
                float p = __expf(Ss[r * 64 + c] - mmax);
                Ss[r * 64 + c] = p;
                lsum += p;
            }
            m_s[r] = mmax; l_s[r] = lsum; resc[r] = rf;
        }
        __syncthreads();

        for (int i = tid; i < 64 * 16; i += 256) {
            int r = i >> 4, d4 = (i & 15) * 4;
            float4 vv = *(const float4*)(V + (size_t)(kt * 64 + r) * KV_DIM + kvh * HEAD_DIM + d4);
            KVs[r * 65 + d4 + 0] = vv.x;
            KVs[r * 65 + d4 + 1] = vv.y;
            KVs[r * 65 + d4 + 2] = vv.z;
            KVs[r * 65 + d4 + 3] = vv.w;
        }
        __syncthreads();

        float rs[4];
#pragma unroll
        for (int i = 0; i < 4; ++i) rs[i] = resc[r0 + i];
#pragma unroll
        for (int i = 0; i < 4; ++i)
#pragma unroll
            for (int j = 0; j < 4; ++j) acc[i][j] *= rs[i];

#pragma unroll 8
        for (int ks = 0; ks < 64; ++ks) {
            float p[4], vv[4];
#pragma unroll
            for (int i = 0; i < 4; ++i) p[i] = Ss[(r0 + i) * 64 + ks];
#pragma unroll
            for (int j = 0; j < 4; ++j) vv[j] = KVs[ks * 65 + c0 + j];
#pragma unroll
            for (int i = 0; i < 4; ++i)
#pragma unroll
                for (int j = 0; j < 4; ++j)
                    acc[i][j] += p[i] * vv[j];
        }
    }
    __syncthreads();

    float linv[4];
#pragma unroll
    for (int i = 0; i < 4; ++i) linv[i] = 1.f / l_s[r0 + i];
#pragma unroll
    for (int i = 0; i < 4; ++i)
#pragma unroll
        for (int j = 0; j < 4; ++j)
            O[(size_t)(qt * 64 + r0 + i) * D_MODEL + h * HEAD_DIM + c0 + j] =
                acc[i][j] * linv[i];
}

// ---------------------------------------------------------------------------
// Launch
// ---------------------------------------------------------------------------
extern "C" void kernel_launch(void* const* d_in, const int* in_sizes, int n_in,
                              void* d_out, int out_size)
{
    const float* x     = (const float*)d_in[0];
    const float* Wq    = (const float*)d_in[1];
    const float* bq    = (const float*)d_in[2];
    const float* Wk    = (const float*)d_in[3];
    const float* bk    = (const float*)d_in[4];
    const float* Wv    = (const float*)d_in[5];
    const float* bv    = (const float*)d_in[6];
    const float* Wo    = (const float*)d_in[7];
    const float* bo    = (const float*)d_in[8];
    const float* freqs = (const float*)d_in[9];
    float* out = (float*)d_out;

    float *qp, *kp, *vp, *ap;
    __nv_bfloat16 *ahi, *alo, *bhi, *blo;
    cudaGetSymbolAddress((void**)&qp, g_q);
    cudaGetSymbolAddress((void**)&kp, g_k);
    cudaGetSymbolAddress((void**)&vp, g_v);
    cudaGetSymbolAddress((void**)&ap, g_attn);
    cudaGetSymbolAddress((void**)&ahi, s_ahi);
    cudaGetSymbolAddress((void**)&alo, s_alo);
    cudaGetSymbolAddress((void**)&bhi, s_bhi);
    cudaGetSymbolAddress((void**)&blo, s_blo);

    cudaFuncSetAttribute(attn_kernel, cudaFuncAttributeMaxDynamicSharedMemorySize,
                         ATTN_SMEM_BYTES);
    cudaFuncSetAttribute(gemm_tc_kernel, cudaFuncAttributeMaxDynamicSharedMemorySize,
                         GEMM_SMEM_BYTES);

    const int n4x = (T_CTX * D_MODEL) / 4;

    // Split x to bf16 hi/lo
    cvt_hilo_kernel<<<(n4x + 255) / 256, 256>>>(x, ahi, alo, n4x);

    // Q = x @ Wq + bq
    cvtT_kernel<<<dim3(D_MODEL / 32, D_MODEL / 32), 256>>>(Wq, bhi, blo, D_MODEL, D_MODEL);
    gemm_tc_kernel<<<dim3(D_MODEL / 128, T_CTX / 128), 256, GEMM_SMEM_BYTES>>>(
        ahi, alo, bhi, blo, bq, qp, T_CTX, D_MODEL, D_MODEL);

    // K = x @ Wk + bk
    cvtT_kernel<<<dim3(KV_DIM / 32, D_MODEL / 32), 256>>>(Wk, bhi, blo, D_MODEL, KV_DIM);
    gemm_tc_kernel<<<dim3(KV_DIM / 128, T_CTX / 128), 256, GEMM_SMEM_BYTES>>>(
        ahi, alo, bhi, blo, bk, kp, T_CTX, KV_DIM, D_MODEL);

    // V = x @ Wv + bv
    cvtT_kernel<<<dim3(KV_DIM / 32, D_MODEL / 32), 256>>>(Wv, bhi, blo, D_MODEL, KV_DIM);
    gemm_tc_kernel<<<dim3(KV_DIM / 128, T_CTX / 128), 256, GEMM_SMEM_BYTES>>>(
        ahi, alo, bhi, blo, bv, vp, T_CTX, KV_DIM, D_MODEL);

    // RoPE
    int tq = T_CTX * N_Q * 32;
    int tk = T_CTX * N_KV * 32;
    rope_kernel<<<(tq + 255) / 256, 256>>>(qp, freqs, N_Q, tq);
    rope_kernel<<<(tk + 255) / 256, 256>>>(kp, freqs, N_KV, tk);

    // Attention
    attn_kernel<<<dim3(N_Q, T_CTX / 64), 256, ATTN_SMEM_BYTES>>>(qp, kp, vp, ap);

    // Out projection
    cvt_hilo_kernel<<<(n4x + 255) / 256, 256>>>(ap, ahi, alo, n4x);
    cvtT_kernel<<<dim3(D_MODEL / 32, D_MODEL / 32), 256>>>(Wo, bhi, blo, D_MODEL, D_MODEL);
    gemm_tc_kernel<<<dim3(D_MODEL / 128, T_CTX / 128), 256, GEMM_SMEM_BYTES>>>(
        ahi, alo, bhi, blo, bo, out, T_CTX, D_MODEL, D_MODEL);
}

// round 4
// speedup vs baseline: 3.3617x; 1.9101x over previous
#include <cuda_runtime.h>
#include <cuda_bf16.h>
#include <cstdint>

// Problem constants
#define T_CTX 2048
#define D_MODEL 2048
#define N_Q 32
#define N_KV 8
#define HEAD_DIM 64
#define KV_DIM (N_KV * HEAD_DIM)   // 512

// ---------------------------------------------------------------------------
// Scratch (allocation-free rule: __device__ globals)
// ---------------------------------------------------------------------------
__device__ __align__(16) float g_q[T_CTX * D_MODEL];
__device__ __align__(16) float g_k[T_CTX * KV_DIM];
__device__ __align__(16) float g_v[T_CTX * KV_DIM];
__device__ __align__(16) float g_attn[T_CTX * D_MODEL];
__device__ __align__(16) __nv_bfloat16 s_ahi[T_CTX * D_MODEL];
__device__ __align__(16) __nv_bfloat16 s_alo[T_CTX * D_MODEL];
__device__ __align__(16) __nv_bfloat16 s_bhi[D_MODEL * D_MODEL];  // W^T [N,K]
__device__ __align__(16) __nv_bfloat16 s_blo[D_MODEL * D_MODEL];
__device__ __align__(16) __nv_bfloat16 s_khi[T_CTX * KV_DIM];
__device__ __align__(16) __nv_bfloat16 s_klo[T_CTX * KV_DIM];
__device__ __align__(16) __nv_bfloat16 s_vhi[T_CTX * KV_DIM];
__device__ __align__(16) __nv_bfloat16 s_vlo[T_CTX * KV_DIM];

// ---------------------------------------------------------------------------
// PTX helpers
// ---------------------------------------------------------------------------
__device__ __forceinline__ uint32_t smem_u32(const void* p) {
    uint32_t a;
    asm("{ .reg .u64 t; cvta.to.shared.u64 t, %1; cvt.u32.u64 %0, t; }"
        : "=r"(a) : "l"(p));
    return a;
}

__device__ __forceinline__ void cp_async16(uint32_t dst, const void* src) {
    asm volatile("cp.async.ca.shared.global [%0], [%1], 16;"
                 :: "r"(dst), "l"(src) : "memory");
}
#define CP_COMMIT() asm volatile("cp.async.commit_group;" ::: "memory")
#define CP_WAIT(n)  asm volatile("cp.async.wait_group %0;" :: "n"(n) : "memory")

__device__ __forceinline__ void ldsm_x4(uint32_t (&r)[4], uint32_t addr) {
    asm volatile("ldmatrix.sync.aligned.m8n8.x4.shared.b16 {%0,%1,%2,%3}, [%4];"
                 : "=r"(r[0]), "=r"(r[1]), "=r"(r[2]), "=r"(r[3]) : "r"(addr));
}

__device__ __forceinline__ void ldsm_x4_t(uint32_t (&r)[4], uint32_t addr) {
    asm volatile("ldmatrix.sync.aligned.m8n8.x4.trans.shared.b16 {%0,%1,%2,%3}, [%4];"
                 : "=r"(r[0]), "=r"(r[1]), "=r"(r[2]), "=r"(r[3]) : "r"(addr));
}

__device__ __forceinline__ void mma16816(float (&d)[4], const uint32_t (&a)[4],
                                         uint32_t b0, uint32_t b1) {
    asm volatile(
        "mma.sync.aligned.m16n8k16.row.col.f32.bf16.bf16.f32 "
        "{%0,%1,%2,%3}, {%4,%5,%6,%7}, {%8,%9}, {%0,%1,%2,%3};"
        : "+f"(d[0]), "+f"(d[1]), "+f"(d[2]), "+f"(d[3])
        : "r"(a[0]), "r"(a[1]), "r"(a[2]), "r"(a[3]), "r"(b0), "r"(b1));
}

__device__ __forceinline__ uint32_t pack_bf16(float x, float y) {
    __nv_bfloat162 t = __floats2bfloat162_rn(x, y);
    return *(uint32_t*)&t;
}

// GEMM smem tile: 128 rows x 32 bf16 (64B rows)
__device__ __forceinline__ uint32_t toff(int r, int c) {
    return (uint32_t)((r << 6) + ((c ^ ((r >> 1) & 3)) << 4));
}
// Attention smem tile: rows of 64 bf16 (128B, 8 chunks of 16B)
__device__ __forceinline__ uint32_t toff128(int r, int c) {
    return (uint32_t)((r << 7) + ((c ^ (r & 7)) << 4));
}

// ---------------------------------------------------------------------------
// bf16-split tensor-core GEMM (unchanged from R3, passing)
// ---------------------------------------------------------------------------
#define GEMM_SMEM_BYTES (2 * 4 * 8192)

__device__ __forceinline__ void stage_load(
    uint32_t stage_base,
    const __nv_bfloat16* __restrict__ Ah, const __nv_bfloat16* __restrict__ Al,
    const __nv_bfloat16* __restrict__ Bh, const __nv_bfloat16* __restrict__ Bl,
    int arow0, int brow0, int k0, int K, int tid)
{
    const __nv_bfloat16* srcs[4] = {Ah, Al, Bh, Bl};
#pragma unroll
    for (int t = 0; t < 4; ++t) {
        const __nv_bfloat16* src = srcs[t];
        const int grow0 = (t < 2) ? arow0 : brow0;
        const uint32_t tb = stage_base + t * 8192;
#pragma unroll
        for (int j = 0; j < 2; ++j) {
            const int idx = j * 256 + tid;
            const int r = idx >> 2;
            const int c = idx & 3;
            cp_async16(tb + toff(r, c),
                       src + (size_t)(grow0 + r) * K + k0 + c * 8);
        }
    }
}

__global__ __launch_bounds__(256, 1) void gemm_tc_kernel(
    const __nv_bfloat16* __restrict__ Ahi, const __nv_bfloat16* __restrict__ Alo,
    const __nv_bfloat16* __restrict__ Bhi, const __nv_bfloat16* __restrict__ Blo,
    const float* __restrict__ bias, float* __restrict__ C,
    int M, int N, int K)
{
    extern __shared__ __align__(1024) char smem_raw[];
    const uint32_t sb = smem_u32(smem_raw);

    const int tid = threadIdx.x;
    const int wid = tid >> 5;
    const int lid = tid & 31;
    const int wm = wid & 1;
    const int wn = wid >> 1;
    const int arow0 = blockIdx.y * 128;
    const int brow0 = blockIdx.x * 128;

    float acc[4][4][4];
#pragma unroll
    for (int i = 0; i < 4; ++i)
#pragma unroll
        for (int j = 0; j < 4; ++j)
#pragma unroll
            for (int q = 0; q < 4; ++q) acc[i][j][q] = 0.f;

    const int NT = K >> 5;

    stage_load(sb, Ahi, Alo, Bhi, Blo, arow0, brow0, 0, K, tid);
    CP_COMMIT();
    stage_load(sb + 32768, Ahi, Alo, Bhi, Blo, arow0, brow0, 32, K, tid);
    CP_COMMIT();

    const int sub = lid >> 3;
    const int l7  = lid & 7;
    const int a_rofs = ((sub & 1) << 3) + l7;
    const int a_cofs = (sub >> 1);
    const int b_rofs = ((sub >> 1) << 3) + l7;
    const int b_cofs = (sub & 1);

    for (int kt = 0; kt < NT; ++kt) {
        if (kt == NT - 1) { CP_WAIT(0); } else { CP_WAIT(1); }
        __syncthreads();

        const uint32_t st = sb + (kt & 1) * 32768;
        const uint32_t tAh = st, tAl = st + 8192, tBh = st + 16384, tBl = st + 24576;

#pragma unroll
        for (int ks = 0; ks < 2; ++ks) {
            const int kc = ks * 2;
            uint32_t ah[4][4], al[4][4];
#pragma unroll
            for (int ma = 0; ma < 4; ++ma) {
                const int row = wm * 64 + ma * 16 + a_rofs;
                const uint32_t o = toff(row, kc + a_cofs);
                ldsm_x4(ah[ma], tAh + o);
                ldsm_x4(al[ma], tAl + o);
            }
            uint32_t bh[2][4], bl[2][4];
#pragma unroll
            for (int nb = 0; nb < 2; ++nb) {
                const int row = wn * 32 + nb * 16 + b_rofs;
                const uint32_t o = toff(row, kc + b_cofs);
                ldsm_x4(bh[nb], tBh + o);
                ldsm_x4(bl[nb], tBl + o);
            }
#pragma unroll
            for (int ma = 0; ma < 4; ++ma) {
#pragma unroll
                for (int na = 0; na < 4; ++na) {
                    const int nb = na >> 1;
                    const int hi2 = (na & 1) << 1;
                    mma16816(acc[ma][na], ah[ma], bh[nb][hi2], bh[nb][hi2 + 1]);
                    mma16816(acc[ma][na], ah[ma], bl[nb][hi2], bl[nb][hi2 + 1]);
                    mma16816(acc[ma][na], al[ma], bh[nb][hi2], bh[nb][hi2 + 1]);
                }
            }
        }
        __syncthreads();

        if (kt + 2 < NT) {
            stage_load(st, Ahi, Alo, Bhi, Blo, arow0, brow0, (kt + 2) << 5, K, tid);
            CP_COMMIT();
        }
    }

    const int er = lid >> 2;
    const int ec = (lid & 3) << 1;
#pragma unroll
    for (int ma = 0; ma < 4; ++ma) {
        const int row = arow0 + wm * 64 + ma * 16 + er;
#pragma unroll
        for (int na = 0; na < 4; ++na) {
            const int col = brow0 + wn * 32 + na * 8 + ec;
            const float b0 = bias[col], b1 = bias[col + 1];
            float2 v0 = make_float2(acc[ma][na][0] + b0, acc[ma][na][1] + b1);
            float2 v1 = make_float2(acc[ma][na][2] + b0, acc[ma][na][3] + b1);
            *(float2*)(C + (size_t)row * N + col) = v0;
            *(float2*)(C + (size_t)(row + 8) * N + col) = v1;
        }
    }
}

// ---------------------------------------------------------------------------
// fp32 -> bf16 hi/lo split
// ---------------------------------------------------------------------------
__global__ void cvt_hilo_kernel(const float* __restrict__ in,
                                __nv_bfloat16* __restrict__ hi,
                                __nv_bfloat16* __restrict__ lo, int n4)
{
    int i = blockIdx.x * blockDim.x + threadIdx.x;
    if (i >= n4) return;
    float4 v = ((const float4*)in)[i];
    __nv_bfloat16 h0 = __float2bfloat16(v.x);
    __nv_bfloat16 h1 = __float2bfloat16(v.y);
    __nv_bfloat16 h2 = __float2bfloat16(v.z);
    __nv_bfloat16 h3 = __float2bfloat16(v.w);
    __nv_bfloat16 l0 = __float2bfloat16(v.x - __bfloat162float(h0));
    __nv_bfloat16 l1 = __float2bfloat16(v.y - __bfloat162float(h1));
    __nv_bfloat16 l2 = __float2bfloat16(v.z - __bfloat162float(h2));
    __nv_bfloat16 l3 = __float2bfloat16(v.w - __bfloat162float(h3));
    uint2 ph, pl;
    ph.x = ((uint32_t)__bfloat16_as_ushort(h1) << 16) | __bfloat16_as_ushort(h0);
    ph.y = ((uint32_t)__bfloat16_as_ushort(h3) << 16) | __bfloat16_as_ushort(h2);
    pl.x = ((uint32_t)__bfloat16_as_ushort(l1) << 16) | __bfloat16_as_ushort(l0);
    pl.y = ((uint32_t)__bfloat16_as_ushort(l3) << 16) | __bfloat16_as_ushort(l2);
    ((uint2*)hi)[i] = ph;
    ((uint2*)lo)[i] = pl;
}

// ---------------------------------------------------------------------------
// Weight transpose + split: W[K,N] fp32 -> hi/lo bf16 [N,K]
// ---------------------------------------------------------------------------
__global__ __launch_bounds__(256) void cvtT_kernel(
    const float* __restrict__ W, __nv_bfloat16* __restrict__ hi,
    __nv_bfloat16* __restrict__ lo, int K, int N)
{
    __shared__ float t[32][33];
    const int nb = blockIdx.x * 32, kb = blockIdx.y * 32;
    const int tx = threadIdx.x & 31, ty = threadIdx.x >> 5;
#pragma unroll
    for (int i = 0; i < 32; i += 8)
        t[ty + i][tx] = W[(size_t)(kb + ty + i) * N + nb + tx];
    __syncthreads();
#pragma unroll
    for (int i = 0; i < 32; i += 8) {
        const int n = nb + ty + i, k = kb + tx;
        const float v = t[tx][ty + i];
        const __nv_bfloat16 h = __float2bfloat16(v);
        hi[(size_t)n * K + k] = h;
        lo[(size_t)n * K + k] = __float2bfloat16(v - __bfloat162float(h));
    }
}

// ---------------------------------------------------------------------------
// RoPE
// ---------------------------------------------------------------------------
__global__ void rope_kernel(float* __restrict__ x, const float* __restrict__ freqs,
                            int nheads, int total)
{
    int idx = blockIdx.x * blockDim.x + threadIdx.x;
    if (idx >= total) return;
    int i = idx & 31;
    int h = (idx >> 5) % nheads;
    int t = idx / (32 * nheads);
    float f = freqs[t * 32 + i];
    float c = cosf(f), s = sinf(f);
    float* base = x + ((size_t)t * nheads + h) * HEAD_DIM;
    float x1 = base[i];
    float x2 = base[i + 32];
    base[i]      = x1 * c - x2 * s;
    base[i + 32] = x1 * s + x2 * c;
}

// ---------------------------------------------------------------------------
// Tensor-core flash attention (causal, GQA), bf16 hi/lo split everywhere.
// CTA = (head, 64 q-rows), 4 warps x 16 rows. KV tiles of 64, double-buffered.
// smem: Qh 8K | Ql 8K | stage0 {Kh,Kl,Vh,Vl}x8K | stage1 same = 80KB
// ---------------------------------------------------------------------------
#define ATT_SMEM (16384 + 2 * 32768)

__global__ __launch_bounds__(128, 2) void attn_tc_kernel(
    const __nv_bfloat16* __restrict__ Qh, const __nv_bfloat16* __restrict__ Ql,
    const __nv_bfloat16* __restrict__ Kh, const __nv_bfloat16* __restrict__ Kl,
    const __nv_bfloat16* __restrict__ Vh, const __nv_bfloat16* __restrict__ Vl,
    float* __restrict__ O)
{
    extern __shared__ __align__(1024) char smem_raw[];
    const uint32_t sb = smem_u32(smem_raw);
    const int tid = threadIdx.x;
    const int wid = tid >> 5;
    const int lid = tid & 31;
    const int h   = blockIdx.x;
    const int bq  = (int)(gridDim.y - 1 - blockIdx.y);   // long tiles first
    const int q0  = bq * 64;
    const int kvh = h >> 2;
    const int nkv = bq + 1;
    const float Cc = 0.125f * 1.44269504088896f;  // scale * log2(e)

    const int sub = lid >> 3;
    const int l7  = lid & 7;
    const int a_rofs = ((sub & 1) << 3) + l7;   // non-trans A / trans-V rows
    const int a_cofs = (sub >> 1);
    const int b_rofs = ((sub >> 1) << 3) + l7;  // non-trans B rows
    const int b_cofs = (sub & 1);

    // Q tile loads (hi at sb, lo at sb+8192)
#pragma unroll
    for (int it = 0; it < 8; ++it) {
        const int idx = it * 128 + tid;
        const int t = idx >> 9, r = (idx >> 3) & 63, c = idx & 7;
        const __nv_bfloat16* src = t ? Ql : Qh;
        cp_async16(sb + t * 8192 + toff128(r, c),
                   src + (size_t)(q0 + r) * D_MODEL + h * HEAD_DIM + c * 8);
    }
    // kv stage 0
    {
        const uint32_t stb = sb + 16384;
        const size_t gofs = (size_t)kvh * HEAD_DIM;
#pragma unroll
        for (int it = 0; it < 16; ++it) {
            const int idx = it * 128 + tid;
            const int t = idx >> 9, r = (idx >> 3) & 63, c = idx & 7;
            const __nv_bfloat16* src = (t == 0) ? Kh : (t == 1) ? Kl : (t == 2) ? Vh : Vl;
            cp_async16(stb + t * 8192 + toff128(r, c),
                       src + gofs + (size_t)r * KV_DIM + c * 8);
        }
    }
    CP_COMMIT();
    if (nkv > 1) {
        const uint32_t stb = sb + 16384 + 32768;
        const size_t gofs = (size_t)64 * KV_DIM + kvh * HEAD_DIM;
#pragma unroll
        for (int it = 0; it < 16; ++it) {
            const int idx = it * 128 + tid;
            const int t = idx >> 9, r = (idx >> 3) & 63, c = idx & 7;
            const __nv_bfloat16* src = (t == 0) ? Kh : (t == 1) ? Kl : (t == 2) ? Vh : Vl;
            cp_async16(stb + t * 8192 + toff128(r, c),
                       src + gofs + (size_t)r * KV_DIM + c * 8);
        }
        CP_COMMIT();
    }

    uint32_t qh[4][4], ql[4][4];
    float oacc[8][4];
#pragma unroll
    for (int nf = 0; nf < 8; ++nf)
#pragma unroll
        for (int q = 0; q < 4; ++q) oacc[nf][q] = 0.f;
    float m0 = -1e30f, m1 = -1e30f, l0 = 0.f, l1 = 0.f;

    for (int kt = 0; kt < nkv; ++kt) {
        if (kt + 1 < nkv) { CP_WAIT(1); } else { CP_WAIT(0); }
        __syncthreads();

        if (kt == 0) {
#pragma unroll
            for (int ks = 0; ks < 4; ++ks) {
                const uint32_t o = toff128(16 * wid + a_rofs, 2 * ks + a_cofs);
                ldsm_x4(qh[ks], sb + o);
                ldsm_x4(ql[ks], sb + 8192 + o);
            }
        }

        const uint32_t stb = sb + 16384 + (kt & 1) * 32768;

        // ---- S = Q @ K^T (hi/lo split) ----
        float sc[8][4];
#pragma unroll
        for (int nf = 0; nf < 8; ++nf)
#pragma unroll
            for (int q = 0; q < 4; ++q) sc[nf][q] = 0.f;

#pragma unroll
        for (int ks = 0; ks < 4; ++ks) {
#pragma unroll
            for (int nb = 0; nb < 4; ++nb) {
                uint32_t khf[4], klf[4];
                const uint32_t o = toff128(16 * nb + b_rofs, 2 * ks + b_cofs);
                ldsm_x4(khf, stb + o);
                ldsm_x4(klf, stb + 8192 + o);
#pragma unroll
                for (int j = 0; j < 2; ++j) {
                    const int nf = 2 * nb + j;
                    const int h2 = j * 2;
                    mma16816(sc[nf], qh[ks], khf[h2], khf[h2 + 1]);
                    mma16816(sc[nf], qh[ks], klf[h2], klf[h2 + 1]);
                    mma16816(sc[nf], ql[ks], khf[h2], khf[h2 + 1]);
                }
            }
        }

        // ---- causal mask (diagonal tile only) ----
        if (kt == bq) {
            const int rloc0 = 16 * wid + (lid >> 2);
#pragma unroll
            for (int nf = 0; nf < 8; ++nf) {
                const int cbase = nf * 8 + ((lid & 3) << 1);
#pragma unroll
                for (int q = 0; q < 4; ++q) {
                    const int col = cbase + (q & 1);
                    const int row = rloc0 + ((q >> 1) << 3);
                    if (col > row) sc[nf][q] = -1e30f;
                }
            }
        }

        // ---- online softmax (per-warp rows, quad shfl reductions) ----
        float vx0 = -1e30f, vx1 = -1e30f;
#pragma unroll
        for (int nf = 0; nf < 8; ++nf) {
            vx0 = fmaxf(vx0, fmaxf(sc[nf][0], sc[nf][1]));
            vx1 = fmaxf(vx1, fmaxf(sc[nf][2], sc[nf][3]));
        }
        vx0 = fmaxf(vx0, __shfl_xor_sync(0xffffffffu, vx0, 1));
        vx0 = fmaxf(vx0, __shfl_xor_sync(0xffffffffu, vx0, 2));
        vx1 = fmaxf(vx1, __shfl_xor_sync(0xffffffffu, vx1, 1));
        vx1 = fmaxf(vx1, __shfl_xor_sync(0xffffffffu, vx1, 2));
        const float mn0 = fmaxf(m0, vx0);
        const float mn1 = fmaxf(m1, vx1);
        const float al0 = exp2f((m0 - mn0) * Cc);
        const float al1 = exp2f((m1 - mn1) * Cc);
        float sum0 = 0.f, sum1 = 0.f;
#pragma unroll
        for (int nf = 0; nf < 8; ++nf) {
            sc[nf][0] = exp2f((sc[nf][0] - mn0) * Cc);
            sc[nf][1] = exp2f((sc[nf][1] - mn0) * Cc);
            sc[nf][2] = exp2f((sc[nf][2] - mn1) * Cc);
            sc[nf][3] = exp2f((sc[nf][3] - mn1) * Cc);
            sum0 += sc[nf][0] + sc[nf][1];
            sum1 += sc[nf][2] + sc[nf][3];
        }
        sum0 += __shfl_xor_sync(0xffffffffu, sum0, 1);
        sum0 += __shfl_xor_sync(0xffffffffu, sum0, 2);
        sum1 += __shfl_xor_sync(0xffffffffu, sum1, 1);
        sum1 += __shfl_xor_sync(0xffffffffu, sum1, 2);
        l0 = l0 * al0 + sum0;
        l1 = l1 * al1 + sum1;
        m0 = mn0; m1 = mn1;
#pragma unroll
        for (int nf = 0; nf < 8; ++nf) {
            oacc[nf][0] *= al0; oacc[nf][1] *= al0;
            oacc[nf][2] *= al1; oacc[nf][3] *= al1;
        }

        // ---- pack P into hi/lo a-frags ----
        uint32_t pah[4][4], pal[4][4];
#pragma unroll
        for (int ks = 0; ks < 4; ++ks) {
#pragma unroll
            for (int part = 0; part < 4; ++part) {
                const int nf = 2 * ks + (part >> 1);
                const int q0i = (part & 1) << 1;  // regs {0,1} or {2,3}
                const float x = sc[nf][q0i], y = sc[nf][q0i + 1];
                const __nv_bfloat16 bx = __float2bfloat16(x);
                const __nv_bfloat16 by = __float2bfloat16(y);
                pah[ks][part] = pack_bf16(__bfloat162float(bx), __bfloat162float(by));
                // re-derive to keep exact hi value used:
                pal[ks][part] = pack_bf16(x - __bfloat162float(bx),
                                          y - __bfloat162float(by));
            }
        }

        // ---- O += P @ V (hi/lo split, V via ldmatrix.trans) ----
#pragma unroll
        for (int ks = 0; ks < 4; ++ks) {
#pragma unroll
            for (int ng = 0; ng < 4; ++ng) {
                uint32_t vhf[4], vlf[4];
                const uint32_t o = toff128(16 * ks + a_rofs, 2 * ng + a_cofs);
                ldsm_x4_t(vhf, stb + 16384 + o);
                ldsm_x4_t(vlf, stb + 24576 + o);
#pragma unroll
                for (int j = 0; j < 2; ++j) {
                    const int nf = 2 * ng + j;
                    const int h2 = j * 2;
                    mma16816(oacc[nf], pah[ks], vhf[h2], vhf[h2 + 1]);
                    mma16816(oacc[nf], pah[ks], vlf[h2], vlf[h2 + 1]);
                    mma16816(oacc[nf], pal[ks], vhf[h2], vhf[h2 + 1]);
                }
            }
        }

        __syncthreads();
        if (kt + 2 < nkv) {
            const uint32_t nstb = sb + 16384 + (kt & 1) * 32768;
            const size_t gofs = (size_t)((kt + 2) * 64) * KV_DIM + kvh * HEAD_DIM;
#pragma unroll
            for (int it = 0; it < 16; ++it) {
                const int idx = it * 128 + tid;
                const int t = idx >> 9, r = (idx >> 3) & 63, c = idx & 7;
                const __nv_bfloat16* src = (t == 0) ? Kh : (t == 1) ? Kl : (t == 2) ? Vh : Vl;
                cp_async16(nstb + t * 8192 + toff128(r, c),
                           src + gofs + (size_t)r * KV_DIM + c * 8);
            }
            CP_COMMIT();
        }
    }

    // ---- epilogue ----
    const float il0 = 1.f / l0;
    const float il1 = 1.f / l1;
    const int row0 = q0 + 16 * wid + (lid >> 2);
    float* o0 = O + (size_t)row0 * D_MODEL + h * HEAD_DIM;
    float* o1 = o0 + (size_t)8 * D_MODEL;
#pragma unroll
    for (int nf = 0; nf < 8; ++nf) {
        const int cc = nf * 8 + ((lid & 3) << 1);
        *(float2*)(o0 + cc) = make_float2(oacc[nf][0] * il0, oacc[nf][1] * il0);
        *(float2*)(o1 + cc) = make_float2(oacc[nf][2] * il1, oacc[nf][3] * il1);
    }
}

// ---------------------------------------------------------------------------
// Launch
// ---------------------------------------------------------------------------
extern "C" void kernel_launch(void* const* d_in, const int* in_sizes, int n_in,
                              void* d_out, int out_size)
{
    const float* x     = (const float*)d_in[0];
    const float* Wq    = (const float*)d_in[1];
    const float* bq    = (const float*)d_in[2];
    const float* Wk    = (const float*)d_in[3];
    const float* bk    = (const float*)d_in[4];
    const float* Wv    = (const float*)d_in[5];
    const float* bv    = (const float*)d_in[6];
    const float* Wo    = (const float*)d_in[7];
    const float* bo    = (const float*)d_in[8];
    const float* freqs = (const float*)d_in[9];
    float* out = (float*)d_out;

    float *qp, *kp, *vp, *ap;
    __nv_bfloat16 *ahi, *alo, *bhi, *blo, *khi, *klo, *vhi, *vlo;
    cudaGetSymbolAddress((void**)&qp, g_q);
    cudaGetSymbolAddress((void**)&kp, g_k);
    cudaGetSymbolAddress((void**)&vp, g_v);
    cudaGetSymbolAddress((void**)&ap, g_attn);
    cudaGetSymbolAddress((void**)&ahi, s_ahi);
    cudaGetSymbolAddress((void**)&alo, s_alo);
    cudaGetSymbolAddress((void**)&bhi, s_bhi);
    cudaGetSymbolAddress((void**)&blo, s_blo);
    cudaGetSymbolAddress((void**)&khi, s_khi);
    cudaGetSymbolAddress((void**)&klo, s_klo);
    cudaGetSymbolAddress((void**)&vhi, s_vhi);
    cudaGetSymbolAddress((void**)&vlo, s_vlo);

    cudaFuncSetAttribute(gemm_tc_kernel, cudaFuncAttributeMaxDynamicSharedMemorySize,
                         GEMM_SMEM_BYTES);
    cudaFuncSetAttribute(attn_tc_kernel, cudaFuncAttributeMaxDynamicSharedMemorySize,
                         ATT_SMEM);

    const int n4x  = (T_CTX * D_MODEL) / 4;
    const int n4kv = (T_CTX * KV_DIM) / 4;

    // Split x to bf16 hi/lo
    cvt_hilo_kernel<<<(n4x + 255) / 256, 256>>>(x, ahi, alo, n4x);

    // Projections
    cvtT_kernel<<<dim3(D_MODEL / 32, D_MODEL / 32), 256>>>(Wq, bhi, blo, D_MODEL, D_MODEL);
    gemm_tc_kernel<<<dim3(D_MODEL / 128, T_CTX / 128), 256, GEMM_SMEM_BYTES>>>(
        ahi, alo, bhi, blo, bq, qp, T_CTX, D_MODEL, D_MODEL);
    cvtT_kernel<<<dim3(KV_DIM / 32, D_MODEL / 32), 256>>>(Wk, bhi, blo, D_MODEL, KV_DIM);
    gemm_tc_kernel<<<dim3(KV_DIM / 128, T_CTX / 128), 256, GEMM_SMEM_BYTES>>>(
        ahi, alo, bhi, blo, bk, kp, T_CTX, KV_DIM, D_MODEL);
    cvtT_kernel<<<dim3(KV_DIM / 32, D_MODEL / 32), 256>>>(Wv, bhi, blo, D_MODEL, KV_DIM);
    gemm_tc_kernel<<<dim3(KV_DIM / 128, T_CTX / 128), 256, GEMM_SMEM_BYTES>>>(
        ahi, alo, bhi, blo, bv, vp, T_CTX, KV_DIM, D_MODEL);

    // RoPE on Q, K
    int tq = T_CTX * N_Q * 32;
    int tk = T_CTX * N_KV * 32;
    rope_kernel<<<(tq + 255) / 256, 256>>>(qp, freqs, N_Q, tq);
    rope_kernel<<<(tk + 255) / 256, 256>>>(kp, freqs, N_KV, tk);

    // Split Q/K/V to bf16 hi/lo (Q reuses s_ahi/s_alo; x-split no longer needed)
    cvt_hilo_kernel<<<(n4x + 255) / 256, 256>>>(qp, ahi, alo, n4x);
    cvt_hilo_kernel<<<(n4kv + 255) / 256, 256>>>(kp, khi, klo, n4kv);
    cvt_hilo_kernel<<<(n4kv + 255) / 256, 256>>>(vp, vhi, vlo, n4kv);

    // Tensor-core flash attention
    attn_tc_kernel<<<dim3(N_Q, T_CTX / 64), 128, ATT_SMEM>>>(
        ahi, alo, khi, klo, vhi, vlo, ap);

    // Out projection
    cvt_hilo_kernel<<<(n4x + 255) / 256, 256>>>(ap, ahi, alo, n4x);
    cvtT_kernel<<<dim3(D_MODEL / 32, D_MODEL / 32), 256>>>(Wo, bhi, blo, D_MODEL, D_MODEL);
    gemm_tc_kernel<<<dim3(D_MODEL / 128, T_CTX / 128), 256, GEMM_SMEM_BYTES>>>(
        ahi, alo, bhi, blo, bo, out, T_CTX, D_MODEL, D_MODEL);
}

// round 5
// speedup vs baseline: 3.9076x; 1.1624x over previous
#include <cuda_runtime.h>
#include <cuda_bf16.h>
#include <cstdint>

// Problem constants
#define T_CTX 2048
#define D_MODEL 2048
#define N_Q 32
#define N_KV 8
#define HEAD_DIM 64
#define KV_DIM (N_KV * HEAD_DIM)   // 512
#define QKV_N (D_MODEL + 2 * KV_DIM)  // 3072

// ---------------------------------------------------------------------------
// Scratch (allocation-free rule: __device__ globals)
// ---------------------------------------------------------------------------
__device__ __align__(16) float g_qkv[T_CTX * QKV_N];
__device__ __align__(16) float g_bias[QKV_N];
__device__ __align__(16) __nv_bfloat16 s_ahi[T_CTX * D_MODEL];
__device__ __align__(16) __nv_bfloat16 s_alo[T_CTX * D_MODEL];
__device__ __align__(16) __nv_bfloat16 s_bhi[QKV_N * D_MODEL];   // W^T [N,K]
__device__ __align__(16) __nv_bfloat16 s_blo[QKV_N * D_MODEL];
__device__ __align__(16) __nv_bfloat16 s_khi[T_CTX * KV_DIM];
__device__ __align__(16) __nv_bfloat16 s_klo[T_CTX * KV_DIM];
__device__ __align__(16) __nv_bfloat16 s_vhi[T_CTX * KV_DIM];
__device__ __align__(16) __nv_bfloat16 s_vlo[T_CTX * KV_DIM];

// ---------------------------------------------------------------------------
// PTX helpers
// ---------------------------------------------------------------------------
__device__ __forceinline__ uint32_t smem_u32(const void* p) {
    uint32_t a;
    asm("{ .reg .u64 t; cvta.to.shared.u64 t, %1; cvt.u32.u64 %0, t; }"
        : "=r"(a) : "l"(p));
    return a;
}

__device__ __forceinline__ void cp_async16(uint32_t dst, const void* src) {
    asm volatile("cp.async.ca.shared.global [%0], [%1], 16;"
                 :: "r"(dst), "l"(src) : "memory");
}
#define CP_COMMIT() asm volatile("cp.async.commit_group;" ::: "memory")
#define CP_WAIT(n)  asm volatile("cp.async.wait_group %0;" :: "n"(n) : "memory")

__device__ __forceinline__ void ldsm_x4(uint32_t (&r)[4], uint32_t addr) {
    asm volatile("ldmatrix.sync.aligned.m8n8.x4.shared.b16 {%0,%1,%2,%3}, [%4];"
                 : "=r"(r[0]), "=r"(r[1]), "=r"(r[2]), "=r"(r[3]) : "r"(addr));
}

__device__ __forceinline__ void ldsm_x4_t(uint32_t (&r)[4], uint32_t addr) {
    asm volatile("ldmatrix.sync.aligned.m8n8.x4.trans.shared.b16 {%0,%1,%2,%3}, [%4];"
                 : "=r"(r[0]), "=r"(r[1]), "=r"(r[2]), "=r"(r[3]) : "r"(addr));
}

__device__ __forceinline__ void mma16816(float (&d)[4], const uint32_t (&a)[4],
                                         uint32_t b0, uint32_t b1) {
    asm volatile(
        "mma.sync.aligned.m16n8k16.row.col.f32.bf16.bf16.f32 "
        "{%0,%1,%2,%3}, {%4,%5,%6,%7}, {%8,%9}, {%0,%1,%2,%3};"
        : "+f"(d[0]), "+f"(d[1]), "+f"(d[2]), "+f"(d[3])
        : "r"(a[0]), "r"(a[1]), "r"(a[2]), "r"(a[3]), "r"(b0), "r"(b1));
}

__device__ __forceinline__ uint32_t pack_bf16(float x, float y) {
    __nv_bfloat162 t = __floats2bfloat162_rn(x, y);
    return *(uint32_t*)&t;
}

// GEMM smem tile: 128 rows x 32 bf16 (64B rows)
__device__ __forceinline__ uint32_t toff(int r, int c) {
    return (uint32_t)((r << 6) + ((c ^ ((r >> 1) & 3)) << 4));
}
// Attention smem tile: rows of 64 bf16 (128B, 8 chunks)
__device__ __forceinline__ uint32_t toff128(int r, int c) {
    return (uint32_t)((r << 7) + ((c ^ (r & 7)) << 4));
}

// ---------------------------------------------------------------------------
// bf16-split tensor-core GEMM, 3-stage cp.async pipeline.
// BM=BN=128, BK=32, 256 threads (8 warps as 2x4), warp tile 64x32.
// ---------------------------------------------------------------------------
#define GEMM_STAGE_BYTES (4 * 8192)
#define GEMM_SMEM_BYTES  (3 * GEMM_STAGE_BYTES)   // 96KB

__device__ __forceinline__ void stage_load(
    uint32_t stage_base,
    const __nv_bfloat16* __restrict__ Ah, const __nv_bfloat16* __restrict__ Al,
    const __nv_bfloat16* __restrict__ Bh, const __nv_bfloat16* __restrict__ Bl,
    int arow0, int brow0, int k0, int K, int tid)
{
    const __nv_bfloat16* srcs[4] = {Ah, Al, Bh, Bl};
#pragma unroll
    for (int t = 0; t < 4; ++t) {
        const __nv_bfloat16* src = srcs[t];
        const int grow0 = (t < 2) ? arow0 : brow0;
        const uint32_t tb = stage_base + t * 8192;
#pragma unroll
        for (int j = 0; j < 2; ++j) {
            const int idx = j * 256 + tid;
            const int r = idx >> 2;
            const int c = idx & 3;
            cp_async16(tb + toff(r, c),
                       src + (size_t)(grow0 + r) * K + k0 + c * 8);
        }
    }
}

__global__ __launch_bounds__(256, 1) void gemm_tc_kernel(
    const __nv_bfloat16* __restrict__ Ahi, const __nv_bfloat16* __restrict__ Alo,
    const __nv_bfloat16* __restrict__ Bhi, const __nv_bfloat16* __restrict__ Blo,
    const float* __restrict__ bias, float* __restrict__ C,
    int M, int N, int K)
{
    extern __shared__ __align__(1024) char smem_raw[];
    const uint32_t sb = smem_u32(smem_raw);

    const int tid = threadIdx.x;
    const int wid = tid >> 5;
    const int lid = tid & 31;
    const int wm = wid & 1;
    const int wn = wid >> 1;
    const int arow0 = blockIdx.y * 128;
    const int brow0 = blockIdx.x * 128;

    float acc[4][4][4];
#pragma unroll
    for (int i = 0; i < 4; ++i)
#pragma unroll
        for (int j = 0; j < 4; ++j)
#pragma unroll
            for (int q = 0; q < 4; ++q) acc[i][j][q] = 0.f;

    const int NT = K >> 5;   // 64 here

    stage_load(sb,                       Ahi, Alo, Bhi, Blo, arow0, brow0, 0,  K, tid);
    CP_COMMIT();
    stage_load(sb + GEMM_STAGE_BYTES,    Ahi, Alo, Bhi, Blo, arow0, brow0, 32, K, tid);
    CP_COMMIT();
    stage_load(sb + 2 * GEMM_STAGE_BYTES, Ahi, Alo, Bhi, Blo, arow0, brow0, 64, K, tid);
    CP_COMMIT();

    const int sub = lid >> 3;
    const int l7  = lid & 7;
    const int a_rofs = ((sub & 1) << 3) + l7;
    const int a_cofs = (sub >> 1);
    const int b_rofs = ((sub >> 1) << 3) + l7;
    const int b_cofs = (sub & 1);

    int slot = 0;
    for (int kt = 0; kt < NT; ++kt) {
        if (kt < NT - 2)       { CP_WAIT(2); }
        else if (kt == NT - 2) { CP_WAIT(1); }
        else                   { CP_WAIT(0); }
        __syncthreads();

        const uint32_t st = sb + slot * GEMM_STAGE_BYTES;
        const uint32_t tAh = st, tAl = st + 8192, tBh = st + 16384, tBl = st + 24576;

#pragma unroll
        for (int ks = 0; ks < 2; ++ks) {
            const int kc = ks * 2;
            uint32_t ah[4][4], al[4][4];
#pragma unroll
            for (int ma = 0; ma < 4; ++ma) {
                const int row = wm * 64 + ma * 16 + a_rofs;
                const uint32_t o = toff(row, kc + a_cofs);
                ldsm_x4(ah[ma], tAh + o);
                ldsm_x4(al[ma], tAl + o);
            }
            uint32_t bh[2][4], bl[2][4];
#pragma unroll
            for (int nb = 0; nb < 2; ++nb) {
                const int row = wn * 32 + nb * 16 + b_rofs;
                const uint32_t o = toff(row, kc + b_cofs);
                ldsm_x4(bh[nb], tBh + o);
                ldsm_x4(bl[nb], tBl + o);
            }
#pragma unroll
            for (int ma = 0; ma < 4; ++ma) {
#pragma unroll
                for (int na = 0; na < 4; ++na) {
                    const int nb = na >> 1;
                    const int hi2 = (na & 1) << 1;
                    mma16816(acc[ma][na], ah[ma], bh[nb][hi2], bh[nb][hi2 + 1]);
                    mma16816(acc[ma][na], ah[ma], bl[nb][hi2], bl[nb][hi2 + 1]);
                    mma16816(acc[ma][na], al[ma], bh[nb][hi2], bh[nb][hi2 + 1]);
                }
            }
        }
        __syncthreads();

        if (kt + 3 < NT) {
            stage_load(st, Ahi, Alo, Bhi, Blo, arow0, brow0, (kt + 3) << 5, K, tid);
            CP_COMMIT();
        }
        slot = (slot == 2) ? 0 : slot + 1;
    }

    const int er = lid >> 2;
    const int ec = (lid & 3) << 1;
#pragma unroll
    for (int ma = 0; ma < 4; ++ma) {
        const int row = arow0 + wm * 64 + ma * 16 + er;
#pragma unroll
        for (int na = 0; na < 4; ++na) {
            const int col = brow0 + wn * 32 + na * 8 + ec;
            const float b0 = bias[col], b1 = bias[col + 1];
            float2 v0 = make_float2(acc[ma][na][0] + b0, acc[ma][na][1] + b1);
            float2 v1 = make_float2(acc[ma][na][2] + b0, acc[ma][na][3] + b1);
            *(float2*)(C + (size_t)row * N + col) = v0;
            *(float2*)(C + (size_t)(row + 8) * N + col) = v1;
        }
    }
}

// ---------------------------------------------------------------------------
// fp32 -> bf16 hi/lo split (for x)
// ---------------------------------------------------------------------------
__global__ void cvt_hilo_kernel(const float* __restrict__ in,
                                __nv_bfloat16* __restrict__ hi,
                                __nv_bfloat16* __restrict__ lo, int n4)
{
    int i = blockIdx.x * blockDim.x + threadIdx.x;
    if (i >= n4) return;
    float4 v = ((const float4*)in)[i];
    __nv_bfloat16 h0 = __float2bfloat16(v.x);
    __nv_bfloat16 h1 = __float2bfloat16(v.y);
    __nv_bfloat16 h2 = __float2bfloat16(v.z);
    __nv_bfloat16 h3 = __float2bfloat16(v.w);
    uint2 ph, pl;
    ph.x = pack_bf16(__bfloat162float(h0), __bfloat162float(h1));
    ph.y = pack_bf16(__bfloat162float(h2), __bfloat162float(h3));
    pl.x = pack_bf16(v.x - __bfloat162float(h0), v.y - __bfloat162float(h1));
    pl.y = pack_bf16(v.z - __bfloat162float(h2), v.w - __bfloat162float(h3));
    ((uint2*)hi)[i] = ph;
    ((uint2*)lo)[i] = pl;
}

// ---------------------------------------------------------------------------
// Weight transpose + split with output row offset: W[K,N] -> hi/lo [rowOfs+N, K]
// ---------------------------------------------------------------------------
__global__ __launch_bounds__(256) void cvtT_kernel(
    const float* __restrict__ W, __nv_bfloat16* __restrict__ hi,
    __nv_bfloat16* __restrict__ lo, int K, int N, int rowOfs)
{
    __shared__ float t[32][33];
    const int nb = blockIdx.x * 32, kb = blockIdx.y * 32;
    const int tx = threadIdx.x & 31, ty = threadIdx.x >> 5;
#pragma unroll
    for (int i = 0; i < 32; i += 8)
        t[ty + i][tx] = W[(size_t)(kb + ty + i) * N + nb + tx];
    __syncthreads();
#pragma unroll
    for (int i = 0; i < 32; i += 8) {
        const int n = rowOfs + nb + ty + i, k = kb + tx;
        const float v = t[tx][ty + i];
        const __nv_bfloat16 h = __float2bfloat16(v);
        hi[(size_t)n * K + k] = h;
        lo[(size_t)n * K + k] = __float2bfloat16(v - __bfloat162float(h));
    }
}

// ---------------------------------------------------------------------------
// Bias concat: [bq | bk | bv]
// ---------------------------------------------------------------------------
__global__ void bias_concat_kernel(const float* __restrict__ bq,
                                   const float* __restrict__ bk,
                                   const float* __restrict__ bv,
                                   float* __restrict__ dst)
{
    int i = blockIdx.x * blockDim.x + threadIdx.x;
    if (i >= QKV_N) return;
    float v;
    if (i < D_MODEL) v = bq[i];
    else if (i < D_MODEL + KV_DIM) v = bk[i - D_MODEL];
    else v = bv[i - D_MODEL - KV_DIM];
    dst[i] = v;
}

// ---------------------------------------------------------------------------
// Fused RoPE + hi/lo split. Reads qkv[T,3072]; writes rope(Q),rope(K) and V
// as bf16 hi/lo. Per t: 1024 q-pairs, 256 k-pairs, 256 v float2s.
// ---------------------------------------------------------------------------
__global__ void rope_split_kernel(const float* __restrict__ qkv,
                                  const float* __restrict__ freqs,
                                  __nv_bfloat16* __restrict__ qhi,
                                  __nv_bfloat16* __restrict__ qlo,
                                  __nv_bfloat16* __restrict__ khi,
                                  __nv_bfloat16* __restrict__ klo,
                                  __nv_bfloat16* __restrict__ vhi,
                                  __nv_bfloat16* __restrict__ vlo)
{
    const int idx = blockIdx.x * blockDim.x + threadIdx.x;
    if (idx >= T_CTX * 1536) return;
    const int t = idx / 1536;
    const int j = idx - t * 1536;

    if (j < 1280) {
        // rotation pair
        const bool isq = (j < 1024);
        const int jj = isq ? j : (j - 1024);
        const int hh = jj >> 5;
        const int i  = jj & 31;
        const float* base = qkv + (size_t)t * QKV_N + (isq ? 0 : D_MODEL) + hh * 64 + i;
        const float x1 = base[0];
        const float x2 = base[32];
        const float f = freqs[t * 32 + i];
        const float c = cosf(f), s = sinf(f);
        const float r1 = x1 * c - x2 * s;
        const float r2 = x1 * s + x2 * c;
        const __nv_bfloat16 h1 = __float2bfloat16(r1);
        const __nv_bfloat16 h2 = __float2bfloat16(r2);
        const int ld = isq ? D_MODEL : KV_DIM;
        __nv_bfloat16* hi = (isq ? qhi : khi) + (size_t)t * ld + hh * 64 + i;
        __nv_bfloat16* lo = (isq ? qlo : klo) + (size_t)t * ld + hh * 64 + i;
        hi[0]  = h1;
        hi[32] = h2;
        lo[0]  = __float2bfloat16(r1 - __bfloat162float(h1));
        lo[32] = __float2bfloat16(r2 - __bfloat162float(h2));
    } else {
        // V: 2 contiguous elements
        const int e0 = (j - 1280) * 2;
        const float2 v = *(const float2*)(qkv + (size_t)t * QKV_N + D_MODEL + KV_DIM + e0);
        const __nv_bfloat16 h0 = __float2bfloat16(v.x);
        const __nv_bfloat16 h1 = __float2bfloat16(v.y);
        *(uint32_t*)(vhi + (size_t)t * KV_DIM + e0) =
            pack_bf16(__bfloat162float(h0), __bfloat162float(h1));
        *(uint32_t*)(vlo + (size_t)t * KV_DIM + e0) =
            pack_bf16(v.x - __bfloat162float(h0), v.y - __bfloat162float(h1));
    }
}

// ---------------------------------------------------------------------------
// Tensor-core flash attention (causal, GQA), bf16 hi/lo split.
// Epilogue writes O directly as bf16 hi/lo (aliasing Q buffers is safe:
// each CTA reads exactly the Q region it later writes, strictly before).
// ---------------------------------------------------------------------------
#define ATT_SMEM (16384 + 2 * 32768)

__global__ __launch_bounds__(128, 2) void attn_tc_kernel(
    const __nv_bfloat16* __restrict__ Qh, const __nv_bfloat16* __restrict__ Ql,
    const __nv_bfloat16* __restrict__ Kh, const __nv_bfloat16* __restrict__ Kl,
    const __nv_bfloat16* __restrict__ Vh, const __nv_bfloat16* __restrict__ Vl,
    __nv_bfloat16* __restrict__ Ohi, __nv_bfloat16* __restrict__ Olo)
{
    extern __shared__ __align__(1024) char smem_raw[];
    const uint32_t sb = smem_u32(smem_raw);
    const int tid = threadIdx.x;
    const int wid = tid >> 5;
    const int lid = tid & 31;
    const int h   = blockIdx.x;
    const int bq  = (int)(gridDim.y - 1 - blockIdx.y);
    const int q0  = bq * 64;
    const int kvh = h >> 2;
    const int nkv = bq + 1;
    const float Cc = 0.125f * 1.44269504088896f;

    const int sub = lid >> 3;
    const int l7  = lid & 7;
    const int a_rofs = ((sub & 1) << 3) + l7;
    const int a_cofs = (sub >> 1);
    const int b_rofs = ((sub >> 1) << 3) + l7;
    const int b_cofs = (sub & 1);

#pragma unroll
    for (int it = 0; it < 8; ++it) {
        const int idx = it * 128 + tid;
        const int t = idx >> 9, r = (idx >> 3) & 63, c = idx & 7;
        const __nv_bfloat16* src = t ? Ql : Qh;
        cp_async16(sb + t * 8192 + toff128(r, c),
                   src + (size_t)(q0 + r) * D_MODEL + h * HEAD_DIM + c * 8);
    }
    {
        const uint32_t stb = sb + 16384;
        const size_t gofs = (size_t)kvh * HEAD_DIM;
#pragma unroll
        for (int it = 0; it < 16; ++it) {
            const int idx = it * 128 + tid;
            const int t = idx >> 9, r = (idx >> 3) & 63, c = idx & 7;
            const __nv_bfloat16* src = (t == 0) ? Kh : (t == 1) ? Kl : (t == 2) ? Vh : Vl;
            cp_async16(stb + t * 8192 + toff128(r, c),
                       src + gofs + (size_t)r * KV_DIM + c * 8);
        }
    }
    CP_COMMIT();
    if (nkv > 1) {
        const uint32_t stb = sb + 16384 + 32768;
        const size_t gofs = (size_t)64 * KV_DIM + kvh * HEAD_DIM;
#pragma unroll
        for (int it = 0; it < 16; ++it) {
            const int idx = it * 128 + tid;
            const int t = idx >> 9, r = (idx >> 3) & 63, c = idx & 7;
            const __nv_bfloat16* src = (t == 0) ? Kh : (t == 1) ? Kl : (t == 2) ? Vh : Vl;
            cp_async16(stb + t * 8192 + toff128(r, c),
                       src + gofs + (size_t)r * KV_DIM + c * 8);
        }
        CP_COMMIT();
    }

    uint32_t qh[4][4], ql[4][4];
    float oacc[8][4];
#pragma unroll
    for (int nf = 0; nf < 8; ++nf)
#pragma unroll
        for (int q = 0; q < 4; ++q) oacc[nf][q] = 0.f;
    float m0 = -1e30f, m1 = -1e30f, l0 = 0.f, l1 = 0.f;

    for (int kt = 0; kt < nkv; ++kt) {
        if (kt + 1 < nkv) { CP_WAIT(1); } else { CP_WAIT(0); }
        __syncthreads();

        if (kt == 0) {
#pragma unroll
            for (int ks = 0; ks < 4; ++ks) {
                const uint32_t o = toff128(16 * wid + a_rofs, 2 * ks + a_cofs);
                ldsm_x4(qh[ks], sb + o);
                ldsm_x4(ql[ks], sb + 8192 + o);
            }
        }

        const uint32_t stb = sb + 16384 + (kt & 1) * 32768;

        float sc[8][4];
#pragma unroll
        for (int nf = 0; nf < 8; ++nf)
#pragma unroll
            for (int q = 0; q < 4; ++q) sc[nf][q] = 0.f;

#pragma unroll
        for (int ks = 0; ks < 4; ++ks) {
#pragma unroll
            for (int nb = 0; nb < 4; ++nb) {
                uint32_t khf[4], klf[4];
                const uint32_t o = toff128(16 * nb + b_rofs, 2 * ks + b_cofs);
                ldsm_x4(khf, stb + o);
                ldsm_x4(klf, stb + 8192 + o);
#pragma unroll
                for (int j = 0; j < 2; ++j) {
                    const int nf = 2 * nb + j;
                    const int h2 = j * 2;
                    mma16816(sc[nf], qh[ks], khf[h2], khf[h2 + 1]);
                    mma16816(sc[nf], qh[ks], klf[h2], klf[h2 + 1]);
                    mma16816(sc[nf], ql[ks], khf[h2], khf[h2 + 1]);
                }
            }
        }

        if (kt == bq) {
            const int rloc0 = 16 * wid + (lid >> 2);
#pragma unroll
            for (int nf = 0; nf < 8; ++nf) {
                const int cbase = nf * 8 + ((lid & 3) << 1);
#pragma unroll
                for (int q = 0; q < 4; ++q) {
                    const int col = cbase + (q & 1);
                    const int row = rloc0 + ((q >> 1) << 3);
                    if (col > row) sc[nf][q] = -1e30f;
                }
            }
        }

        float vx0 = -1e30f, vx1 = -1e30f;
#pragma unroll
        for (int nf = 0; nf < 8; ++nf) {
            vx0 = fmaxf(vx0, fmaxf(sc[nf][0], sc[nf][1]));
            vx1 = fmaxf(vx1, fmaxf(sc[nf][2], sc[nf][3]));
        }
        vx0 = fmaxf(vx0, __shfl_xor_sync(0xffffffffu, vx0, 1));
        vx0 = fmaxf(vx0, __shfl_xor_sync(0xffffffffu, vx0, 2));
        vx1 = fmaxf(vx1, __shfl_xor_sync(0xffffffffu, vx1, 1));
        vx1 = fmaxf(vx1, __shfl_xor_sync(0xffffffffu, vx1, 2));
        const float mn0 = fmaxf(m0, vx0);
        const float mn1 = fmaxf(m1, vx1);
        const float al0 = exp2f((m0 - mn0) * Cc);
        const float al1 = exp2f((m1 - mn1) * Cc);
        float sum0 = 0.f, sum1 = 0.f;
#pragma unroll
        for (int nf = 0; nf < 8; ++nf) {
            sc[nf][0] = exp2f((sc[nf][0] - mn0) * Cc);
            sc[nf][1] = exp2f((sc[nf][1] - mn0) * Cc);
            sc[nf][2] = exp2f((sc[nf][2] - mn1) * Cc);
            sc[nf][3] = exp2f((sc[nf][3] - mn1) * Cc);
            sum0 += sc[nf][0] + sc[nf][1];
            sum1 += sc[nf][2] + sc[nf][3];
        }
        sum0 += __shfl_xor_sync(0xffffffffu, sum0, 1);
        sum0 += __shfl_xor_sync(0xffffffffu, sum0, 2);
        sum1 += __shfl_xor_sync(0xffffffffu, sum1, 1);
        sum1 += __shfl_xor_sync(0xffffffffu, sum1, 2);
        l0 = l0 * al0 + sum0;
        l1 = l1 * al1 + sum1;
        m0 = mn0; m1 = mn1;
#pragma unroll
        for (int nf = 0; nf < 8; ++nf) {
            oacc[nf][0] *= al0; oacc[nf][1] *= al0;
            oacc[nf][2] *= al1; oacc[nf][3] *= al1;
        }

        uint32_t pah[4][4], pal[4][4];
#pragma unroll
        for (int ks = 0; ks < 4; ++ks) {
#pragma unroll
            for (int part = 0; part < 4; ++part) {
                const int nf = 2 * ks + (part >> 1);
                const int q0i = (part & 1) << 1;
                const float x = sc[nf][q0i], y = sc[nf][q0i + 1];
                const __nv_bfloat16 bx = __float2bfloat16(x);
                const __nv_bfloat16 by = __float2bfloat16(y);
                pah[ks][part] = pack_bf16(__bfloat162float(bx), __bfloat162float(by));
                pal[ks][part] = pack_bf16(x - __bfloat162float(bx),
                                          y - __bfloat162float(by));
            }
        }

#pragma unroll
        for (int ks = 0; ks < 4; ++ks) {
#pragma unroll
            for (int ng = 0; ng < 4; ++ng) {
                uint32_t vhf[4], vlf[4];
                const uint32_t o = toff128(16 * ks + a_rofs, 2 * ng + a_cofs);
                ldsm_x4_t(vhf, stb + 16384 + o);
                ldsm_x4_t(vlf, stb + 24576 + o);
#pragma unroll
                for (int j = 0; j < 2; ++j) {
                    const int nf = 2 * ng + j;
                    const int h2 = j * 2;
                    mma16816(oacc[nf], pah[ks], vhf[h2], vhf[h2 + 1]);
                    mma16816(oacc[nf], pah[ks], vlf[h2], vlf[h2 + 1]);
                    mma16816(oacc[nf], pal[ks], vhf[h2], vhf[h2 + 1]);
                }
            }
        }

        __syncthreads();
        if (kt + 2 < nkv) {
            const uint32_t nstb = sb + 16384 + (kt & 1) * 32768;
            const size_t gofs = (size_t)((kt + 2) * 64) * KV_DIM + kvh * HEAD_DIM;
#pragma unroll
            for (int it = 0; it < 16; ++it) {
                const int idx = it * 128 + tid;
                const int t = idx >> 9, r = (idx >> 3) & 63, c = idx & 7;
                const __nv_bfloat16* src = (t == 0) ? Kh : (t == 1) ? Kl : (t == 2) ? Vh : Vl;
                cp_async16(nstb + t * 8192 + toff128(r, c),
                           src + gofs + (size_t)r * KV_DIM + c * 8);
            }
            CP_COMMIT();
        }
    }

    // ---- epilogue: normalize, split hi/lo, write bf16 ----
    const float il0 = 1.f / l0;
    const float il1 = 1.f / l1;
    const int row0 = q0 + 16 * wid + (lid >> 2);
    const size_t base0 = (size_t)row0 * D_MODEL + h * HEAD_DIM;
    const size_t base1 = base0 + (size_t)8 * D_MODEL;
#pragma unroll
    for (int nf = 0; nf < 8; ++nf) {
        const int cc = nf * 8 + ((lid & 3) << 1);
        const float a0 = oacc[nf][0] * il0, a1 = oacc[nf][1] * il0;
        const float b0 = oacc[nf][2] * il1, b1 = oacc[nf][3] * il1;
        const __nv_bfloat16 ha0 = __float2bfloat16(a0), ha1 = __float2bfloat16(a1);
        const __nv_bfloat16 hb0 = __float2bfloat16(b0), hb1 = __float2bfloat16(b1);
        *(uint32_t*)(Ohi + base0 + cc) = pack_bf16(__bfloat162float(ha0), __bfloat162float(ha1));
        *(uint32_t*)(Olo + base0 + cc) = pack_bf16(a0 - __bfloat162float(ha0),
                                                   a1 - __bfloat162float(ha1));
        *(uint32_t*)(Ohi + base1 + cc) = pack_bf16(__bfloat162float(hb0), __bfloat162float(hb1));
        *(uint32_t*)(Olo + base1 + cc) = pack_bf16(b0 - __bfloat162float(hb0),
                                                   b1 - __bfloat162float(hb1));
    }
}

// ---------------------------------------------------------------------------
// Launch
// ---------------------------------------------------------------------------
extern "C" void kernel_launch(void* const* d_in, const int* in_sizes, int n_in,
                              void* d_out, int out_size)
{
    const float* x     = (const float*)d_in[0];
    const float* Wq    = (const float*)d_in[1];
    const float* bq    = (const float*)d_in[2];
    const float* Wk    = (const float*)d_in[3];
    const float* bk    = (const float*)d_in[4];
    const float* Wv    = (const float*)d_in[5];
    const float* bv    = (const float*)d_in[6];
    const float* Wo    = (const float*)d_in[7];
    const float* bo    = (const float*)d_in[8];
    const float* freqs = (const float*)d_in[9];
    float* out = (float*)d_out;

    float *qkvp, *biasp;
    __nv_bfloat16 *ahi, *alo, *bhi, *blo, *khi, *klo, *vhi, *vlo;
    cudaGetSymbolAddress((void**)&qkvp, g_qkv);
    cudaGetSymbolAddress((void**)&biasp, g_bias);
    cudaGetSymbolAddress((void**)&ahi, s_ahi);
    cudaGetSymbolAddress((void**)&alo, s_alo);
    cudaGetSymbolAddress((void**)&bhi, s_bhi);
    cudaGetSymbolAddress((void**)&blo, s_blo);
    cudaGetSymbolAddress((void**)&khi, s_khi);
    cudaGetSymbolAddress((void**)&klo, s_klo);
    cudaGetSymbolAddress((void**)&vhi, s_vhi);
    cudaGetSymbolAddress((void**)&vlo, s_vlo);

    cudaFuncSetAttribute(gemm_tc_kernel, cudaFuncAttributeMaxDynamicSharedMemorySize,
                         GEMM_SMEM_BYTES);
    cudaFuncSetAttribute(attn_tc_kernel, cudaFuncAttributeMaxDynamicSharedMemorySize,
                         ATT_SMEM);

    const int n4x = (T_CTX * D_MODEL) / 4;

    // x -> bf16 hi/lo (A operand for QKV GEMM)
    cvt_hilo_kernel<<<(n4x + 255) / 256, 256>>>(x, ahi, alo, n4x);

    // Combined transposed weights [3072, 2048] and bias [3072]
    cvtT_kernel<<<dim3(D_MODEL / 32, D_MODEL / 32), 256>>>(Wq, bhi, blo, D_MODEL, D_MODEL, 0);
    cvtT_kernel<<<dim3(KV_DIM / 32, D_MODEL / 32), 256>>>(Wk, bhi, blo, D_MODEL, KV_DIM, D_MODEL);
    cvtT_kernel<<<dim3(KV_DIM / 32, D_MODEL / 32), 256>>>(Wv, bhi, blo, D_MODEL, KV_DIM, D_MODEL + KV_DIM);
    bias_concat_kernel<<<(QKV_N + 255) / 256, 256>>>(bq, bk, bv, biasp);

    // Fused QKV GEMM: [2048, 3072]
    gemm_tc_kernel<<<dim3(QKV_N / 128, T_CTX / 128), 256, GEMM_SMEM_BYTES>>>(
        ahi, alo, bhi, blo, biasp, qkvp, T_CTX, QKV_N, D_MODEL);

    // Fused RoPE + hi/lo split (Q into ahi/alo, K/V into dedicated buffers)
    {
        const int total = T_CTX * 1536;
        rope_split_kernel<<<(total + 255) / 256, 256>>>(
            qkvp, freqs, ahi, alo, khi, klo, vhi, vlo);
    }

    // Tensor-core flash attention; epilogue writes O hi/lo into ahi/alo
    attn_tc_kernel<<<dim3(N_Q, T_CTX / 64), 128, ATT_SMEM>>>(
        ahi, alo, khi, klo, vhi, vlo, ahi, alo);

    // Out projection
    cvtT_kernel<<<dim3(D_MODEL / 32, D_MODEL / 32), 256>>>(Wo, bhi, blo, D_MODEL, D_MODEL, 0);
    gemm_tc_kernel<<<dim3(D_MODEL / 128, T_CTX / 128), 256, GEMM_SMEM_BYTES>>>(
        ahi, alo, bhi, blo, bo, out, T_CTX, D_MODEL, D_MODEL);
}

// round 6
// speedup vs baseline: 3.9889x; 1.0208x over previous
#include <cuda_runtime.h>
#include <cuda_bf16.h>
#include <cstdint>

// Problem constants
#define T_CTX 2048
#define D_MODEL 2048
#define N_Q 32
#define N_KV 8
#define HEAD_DIM 64
#define KV_DIM (N_KV * HEAD_DIM)      // 512
#define QKV_N (D_MODEL + 2 * KV_DIM)  // 3072

// ---------------------------------------------------------------------------
// Scratch (allocation-free rule: __device__ globals)
// ---------------------------------------------------------------------------
__device__ __align__(16) float g_bias[QKV_N];
__device__ __align__(16) __nv_bfloat16 s_ahi[T_CTX * D_MODEL];   // x-split, then O
__device__ __align__(16) __nv_bfloat16 s_alo[T_CTX * D_MODEL];
__device__ __align__(16) __nv_bfloat16 s_qhi[T_CTX * D_MODEL];
__device__ __align__(16) __nv_bfloat16 s_qlo[T_CTX * D_MODEL];
__device__ __align__(16) __nv_bfloat16 s_bhi[QKV_N * D_MODEL];   // W^T [N,K]
__device__ __align__(16) __nv_bfloat16 s_blo[QKV_N * D_MODEL];
__device__ __align__(16) __nv_bfloat16 s_khi[T_CTX * KV_DIM];
__device__ __align__(16) __nv_bfloat16 s_klo[T_CTX * KV_DIM];
__device__ __align__(16) __nv_bfloat16 s_vhi[T_CTX * KV_DIM];
__device__ __align__(16) __nv_bfloat16 s_vlo[T_CTX * KV_DIM];

// ---------------------------------------------------------------------------
// PTX helpers
// ---------------------------------------------------------------------------
__device__ __forceinline__ uint32_t smem_u32(const void* p) {
    uint32_t a;
    asm("{ .reg .u64 t; cvta.to.shared.u64 t, %1; cvt.u32.u64 %0, t; }"
        : "=r"(a) : "l"(p));
    return a;
}

__device__ __forceinline__ void cp_async16(uint32_t dst, const void* src) {
    asm volatile("cp.async.ca.shared.global [%0], [%1], 16;"
                 :: "r"(dst), "l"(src) : "memory");
}
#define CP_COMMIT() asm volatile("cp.async.commit_group;" ::: "memory")
#define CP_WAIT(n)  asm volatile("cp.async.wait_group %0;" :: "n"(n) : "memory")

__device__ __forceinline__ void ldsm_x4(uint32_t (&r)[4], uint32_t addr) {
    asm volatile("ldmatrix.sync.aligned.m8n8.x4.shared.b16 {%0,%1,%2,%3}, [%4];"
                 : "=r"(r[0]), "=r"(r[1]), "=r"(r[2]), "=r"(r[3]) : "r"(addr));
}

__device__ __forceinline__ void ldsm_x4_t(uint32_t (&r)[4], uint32_t addr) {
    asm volatile("ldmatrix.sync.aligned.m8n8.x4.trans.shared.b16 {%0,%1,%2,%3}, [%4];"
                 : "=r"(r[0]), "=r"(r[1]), "=r"(r[2]), "=r"(r[3]) : "r"(addr));
}

__device__ __forceinline__ void mma16816(float (&d)[4], const uint32_t (&a)[4],
                                         uint32_t b0, uint32_t b1) {
    asm volatile(
        "mma.sync.aligned.m16n8k16.row.col.f32.bf16.bf16.f32 "
        "{%0,%1,%2,%3}, {%4,%5,%6,%7}, {%8,%9}, {%0,%1,%2,%3};"
        : "+f"(d[0]), "+f"(d[1]), "+f"(d[2]), "+f"(d[3])
        : "r"(a[0]), "r"(a[1]), "r"(a[2]), "r"(a[3]), "r"(b0), "r"(b1));
}

__device__ __forceinline__ uint32_t pack_bf16(float x, float y) {
    __nv_bfloat162 t = __floats2bfloat162_rn(x, y);
    return *(uint32_t*)&t;
}

// GEMM smem tile: 128 rows x 32 bf16 (64B rows)
__device__ __forceinline__ uint32_t toff(int r, int c) {
    return (uint32_t)((r << 6) + ((c ^ ((r >> 1) & 3)) << 4));
}
// Attention smem tile: rows of 64 bf16 (128B, 8 chunks)
__device__ __forceinline__ uint32_t toff128(int r, int c) {
    return (uint32_t)((r << 7) + ((c ^ (r & 7)) << 4));
}

// ---------------------------------------------------------------------------
// bf16-split tensor-core GEMM, 3-stage cp.async pipeline.
// mode 0: C = fp32 out + bias.  mode 1: fused bias+RoPE+hi/lo split epilogue.
// ---------------------------------------------------------------------------
#define GEMM_STAGE_BYTES (4 * 8192)
#define GEMM_SMEM_BYTES  (3 * GEMM_STAGE_BYTES)   // 96KB

__device__ __forceinline__ void stage_load(
    uint32_t stage_base,
    const __nv_bfloat16* __restrict__ Ah, const __nv_bfloat16* __restrict__ Al,
    const __nv_bfloat16* __restrict__ Bh, const __nv_bfloat16* __restrict__ Bl,
    int arow0, int brow0, int k0, int K, int tid)
{
    const __nv_bfloat16* srcs[4] = {Ah, Al, Bh, Bl};
#pragma unroll
    for (int t = 0; t < 4; ++t) {
        const __nv_bfloat16* src = srcs[t];
        const int grow0 = (t < 2) ? arow0 : brow0;
        const uint32_t tb = stage_base + t * 8192;
#pragma unroll
        for (int j = 0; j < 2; ++j) {
            const int idx = j * 256 + tid;
            const int r = idx >> 2;
            const int c = idx & 3;
            cp_async16(tb + toff(r, c),
                       src + (size_t)(grow0 + r) * K + k0 + c * 8);
        }
    }
}

__global__ __launch_bounds__(256, 1) void gemm_tc_kernel(
    const __nv_bfloat16* __restrict__ Ahi, const __nv_bfloat16* __restrict__ Alo,
    const __nv_bfloat16* __restrict__ Bhi, const __nv_bfloat16* __restrict__ Blo,
    const float* __restrict__ bias, float* __restrict__ C,
    int M, int N, int K, int mode,
    const float* __restrict__ freqs,
    __nv_bfloat16* __restrict__ qhi, __nv_bfloat16* __restrict__ qlo,
    __nv_bfloat16* __restrict__ khi, __nv_bfloat16* __restrict__ klo,
    __nv_bfloat16* __restrict__ vhi, __nv_bfloat16* __restrict__ vlo)
{
    extern __shared__ __align__(1024) char smem_raw[];
    const uint32_t sb = smem_u32(smem_raw);

    const int tid = threadIdx.x;
    const int wid = tid >> 5;
    const int lid = tid & 31;
    const int wm = wid & 1;
    const int wn = wid >> 1;
    const int arow0 = blockIdx.y * 128;
    const int brow0 = blockIdx.x * 128;

    float acc[4][4][4];
#pragma unroll
    for (int i = 0; i < 4; ++i)
#pragma unroll
        for (int j = 0; j < 4; ++j)
#pragma unroll
            for (int q = 0; q < 4; ++q) acc[i][j][q] = 0.f;

    const int NT = K >> 5;

    stage_load(sb,                        Ahi, Alo, Bhi, Blo, arow0, brow0, 0,  K, tid);
    CP_COMMIT();
    stage_load(sb + GEMM_STAGE_BYTES,     Ahi, Alo, Bhi, Blo, arow0, brow0, 32, K, tid);
    CP_COMMIT();
    stage_load(sb + 2 * GEMM_STAGE_BYTES, Ahi, Alo, Bhi, Blo, arow0, brow0, 64, K, tid);
    CP_COMMIT();

    const int sub = lid >> 3;
    const int l7  = lid & 7;
    const int a_rofs = ((sub & 1) << 3) + l7;
    const int a_cofs = (sub >> 1);
    const int b_rofs = ((sub >> 1) << 3) + l7;
    const int b_cofs = (sub & 1);

    int slot = 0;
    for (int kt = 0; kt < NT; ++kt) {
        if (kt < NT - 2)       { CP_WAIT(2); }
        else if (kt == NT - 2) { CP_WAIT(1); }
        else                   { CP_WAIT(0); }
        __syncthreads();

        const uint32_t st = sb + slot * GEMM_STAGE_BYTES;
        const uint32_t tAh = st, tAl = st + 8192, tBh = st + 16384, tBl = st + 24576;

#pragma unroll
        for (int ks = 0; ks < 2; ++ks) {
            const int kc = ks * 2;
            uint32_t ah[4][4], al[4][4];
#pragma unroll
            for (int ma = 0; ma < 4; ++ma) {
                const int row = wm * 64 + ma * 16 + a_rofs;
                const uint32_t o = toff(row, kc + a_cofs);
                ldsm_x4(ah[ma], tAh + o);
                ldsm_x4(al[ma], tAl + o);
            }
            uint32_t bh[2][4], bl[2][4];
#pragma unroll
            for (int nb = 0; nb < 2; ++nb) {
                const int row = wn * 32 + nb * 16 + b_rofs;
                const uint32_t o = toff(row, kc + b_cofs);
                ldsm_x4(bh[nb], tBh + o);
                ldsm_x4(bl[nb], tBl + o);
            }
#pragma unroll
            for (int ma = 0; ma < 4; ++ma) {
#pragma unroll
                for (int na = 0; na < 4; ++na) {
                    const int nb = na >> 1;
                    const int hi2 = (na & 1) << 1;
                    mma16816(acc[ma][na], ah[ma], bh[nb][hi2], bh[nb][hi2 + 1]);
                    mma16816(acc[ma][na], ah[ma], bl[nb][hi2], bl[nb][hi2 + 1]);
                    mma16816(acc[ma][na], al[ma], bh[nb][hi2], bh[nb][hi2 + 1]);
                }
            }
        }
        __syncthreads();

        if (kt + 3 < NT) {
            stage_load(st, Ahi, Alo, Bhi, Blo, arow0, brow0, (kt + 3) << 5, K, tid);
            CP_COMMIT();
        }
        slot = (slot == 2) ? 0 : slot + 1;
    }

    const int er = lid >> 2;
    const int ec = (lid & 3) << 1;

    if (mode == 0) {
        // plain fp32 epilogue with bias
#pragma unroll
        for (int ma = 0; ma < 4; ++ma) {
            const int row = arow0 + wm * 64 + ma * 16 + er;
#pragma unroll
            for (int na = 0; na < 4; ++na) {
                const int col = brow0 + wn * 32 + na * 8 + ec;
                const float b0 = bias[col], b1 = bias[col + 1];
                float2 v0 = make_float2(acc[ma][na][0] + b0, acc[ma][na][1] + b1);
                float2 v1 = make_float2(acc[ma][na][2] + b0, acc[ma][na][3] + b1);
                *(float2*)(C + (size_t)row * N + col) = v0;
                *(float2*)(C + (size_t)(row + 8) * N + col) = v1;
            }
        }
        return;
    }

    // ---- mode 1: fused bias + RoPE + hi/lo split epilogue ----
    // Stage the 128x128 fp32 tile (with bias) into smem [128][132].
    float* cs = (float*)smem_raw;
#pragma unroll
    for (int ma = 0; ma < 4; ++ma) {
        const int rl0 = wm * 64 + ma * 16 + er;
#pragma unroll
        for (int na = 0; na < 4; ++na) {
            const int cl = wn * 32 + na * 8 + ec;
            const float b0 = bias[brow0 + cl], b1 = bias[brow0 + cl + 1];
            cs[rl0 * 132 + cl]             = acc[ma][na][0] + b0;
            cs[rl0 * 132 + cl + 1]         = acc[ma][na][1] + b1;
            cs[(rl0 + 8) * 132 + cl]       = acc[ma][na][2] + b0;
            cs[(rl0 + 8) * 132 + cl + 1]   = acc[ma][na][3] + b1;
        }
    }
    __syncthreads();

    // Tile columns lie entirely within Q [0,2048), K [2048,2560), or V [2560,3072)
    if (brow0 < D_MODEL + KV_DIM) {
        // Q or K: rope pairs (d, d+32) within each 64-wide head; tile = 2 heads.
        const bool isq = (brow0 < D_MODEL);
        __nv_bfloat16* hi = isq ? qhi : khi;
        __nv_bfloat16* lo = isq ? qlo : klo;
        const int ld = isq ? D_MODEL : KV_DIM;
        const int colbase = isq ? brow0 : (brow0 - D_MODEL);
#pragma unroll
        for (int p = tid; p < 128 * 64; p += 256) {
            const int r  = p >> 6;
            const int pc = p & 63;
            const int h2 = pc >> 5;
            const int d  = pc & 31;
            const int c1 = (h2 << 6) + d;
            const float x1 = cs[r * 132 + c1];
            const float x2 = cs[r * 132 + c1 + 32];
            const int t = arow0 + r;
            const float f = freqs[t * 32 + d];
            float sn, csn;
            __sincosf(f, &sn, &csn);
            const float r1 = x1 * csn - x2 * sn;
            const float r2 = x1 * sn + x2 * csn;
            const __nv_bfloat16 h1 = __float2bfloat16(r1);
            const __nv_bfloat16 h2b = __float2bfloat16(r2);
            const size_t o1 = (size_t)t * ld + colbase + c1;
            hi[o1]      = h1;
            hi[o1 + 32] = h2b;
            lo[o1]      = __float2bfloat16(r1 - __bfloat162float(h1));
            lo[o1 + 32] = __float2bfloat16(r2 - __bfloat162float(h2b));
        }
    } else {
        // V: plain split
        const int colbase = brow0 - (D_MODEL + KV_DIM);
#pragma unroll
        for (int p = tid; p < 128 * 64; p += 256) {
            const int r = p >> 6;
            const int c = (p & 63) << 1;
            const float x0 = cs[r * 132 + c];
            const float x1 = cs[r * 132 + c + 1];
            const __nv_bfloat16 h0 = __float2bfloat16(x0);
            const __nv_bfloat16 h1 = __float2bfloat16(x1);
            const size_t o = (size_t)(arow0 + r) * KV_DIM + colbase + c;
            *(uint32_t*)(vhi + o) = pack_bf16(__bfloat162float(h0), __bfloat162float(h1));
            *(uint32_t*)(vlo + o) = pack_bf16(x0 - __bfloat162float(h0),
                                              x1 - __bfloat162float(h1));
        }
    }
}

// ---------------------------------------------------------------------------
// fp32 -> bf16 hi/lo split (for x)
// ---------------------------------------------------------------------------
__global__ void cvt_hilo_kernel(const float* __restrict__ in,
                                __nv_bfloat16* __restrict__ hi,
                                __nv_bfloat16* __restrict__ lo, int n4)
{
    int i = blockIdx.x * blockDim.x + threadIdx.x;
    if (i >= n4) return;
    float4 v = ((const float4*)in)[i];
    __nv_bfloat16 h0 = __float2bfloat16(v.x);
    __nv_bfloat16 h1 = __float2bfloat16(v.y);
    __nv_bfloat16 h2 = __float2bfloat16(v.z);
    __nv_bfloat16 h3 = __float2bfloat16(v.w);
    uint2 ph, pl;
    ph.x = pack_bf16(__bfloat162float(h0), __bfloat162float(h1));
    ph.y = pack_bf16(__bfloat162float(h2), __bfloat162float(h3));
    pl.x = pack_bf16(v.x - __bfloat162float(h0), v.y - __bfloat162float(h1));
    pl.y = pack_bf16(v.z - __bfloat162float(h2), v.w - __bfloat162float(h3));
    ((uint2*)hi)[i] = ph;
    ((uint2*)lo)[i] = pl;
}

// ---------------------------------------------------------------------------
// Weight transpose + split with output row offset
// ---------------------------------------------------------------------------
__global__ __launch_bounds__(256) void cvtT_kernel(
    const float* __restrict__ W, __nv_bfloat16* __restrict__ hi,
    __nv_bfloat16* __restrict__ lo, int K, int N, int rowOfs)
{
    __shared__ float t[32][33];
    const int nb = blockIdx.x * 32, kb = blockIdx.y * 32;
    const int tx = threadIdx.x & 31, ty = threadIdx.x >> 5;
#pragma unroll
    for (int i = 0; i < 32; i += 8)
        t[ty + i][tx] = W[(size_t)(kb + ty + i) * N + nb + tx];
    __syncthreads();
#pragma unroll
    for (int i = 0; i < 32; i += 8) {
        const int n = rowOfs + nb + ty + i, k = kb + tx;
        const float v = t[tx][ty + i];
        const __nv_bfloat16 h = __float2bfloat16(v);
        hi[(size_t)n * K + k] = h;
        lo[(size_t)n * K + k] = __float2bfloat16(v - __bfloat162float(h));
    }
}

// ---------------------------------------------------------------------------
// Bias concat: [bq | bk | bv]
// ---------------------------------------------------------------------------
__global__ void bias_concat_kernel(const float* __restrict__ bq,
                                   const float* __restrict__ bk,
                                   const float* __restrict__ bv,
                                   float* __restrict__ dst)
{
    int i = blockIdx.x * blockDim.x + threadIdx.x;
    if (i >= QKV_N) return;
    float v;
    if (i < D_MODEL) v = bq[i];
    else if (i < D_MODEL + KV_DIM) v = bk[i - D_MODEL];
    else v = bv[i - D_MODEL - KV_DIM];
    dst[i] = v;
}

// ---------------------------------------------------------------------------
// Tensor-core flash attention (causal, GQA), bf16 hi/lo split.
// ---------------------------------------------------------------------------
#define ATT_SMEM (16384 + 2 * 32768)

__global__ __launch_bounds__(128, 2) void attn_tc_kernel(
    const __nv_bfloat16* __restrict__ Qh, const __nv_bfloat16* __restrict__ Ql,
    const __nv_bfloat16* __restrict__ Kh, const __nv_bfloat16* __restrict__ Kl,
    const __nv_bfloat16* __restrict__ Vh, const __nv_bfloat16* __restrict__ Vl,
    __nv_bfloat16* __restrict__ Ohi, __nv_bfloat16* __restrict__ Olo)
{
    extern __shared__ __align__(1024) char smem_raw[];
    const uint32_t sb = smem_u32(smem_raw);
    const int tid = threadIdx.x;
    const int wid = tid >> 5;
    const int lid = tid & 31;
    const int h   = blockIdx.x;
    const int bq  = (int)(gridDim.y - 1 - blockIdx.y);
    const int q0  = bq * 64;
    const int kvh = h >> 2;
    const int nkv = bq + 1;
    const float Cc = 0.125f * 1.44269504088896f;

    const int sub = lid >> 3;
    const int l7  = lid & 7;
    const int a_rofs = ((sub & 1) << 3) + l7;
    const int a_cofs = (sub >> 1);
    const int b_rofs = ((sub >> 1) << 3) + l7;
    const int b_cofs = (sub & 1);

#pragma unroll
    for (int it = 0; it < 8; ++it) {
        const int idx = it * 128 + tid;
        const int t = idx >> 9, r = (idx >> 3) & 63, c = idx & 7;
        const __nv_bfloat16* src = t ? Ql : Qh;
        cp_async16(sb + t * 8192 + toff128(r, c),
                   src + (size_t)(q0 + r) * D_MODEL + h * HEAD_DIM + c * 8);
    }
    {
        const uint32_t stb = sb + 16384;
        const size_t gofs = (size_t)kvh * HEAD_DIM;
#pragma unroll
        for (int it = 0; it < 16; ++it) {
            const int idx = it * 128 + tid;
            const int t = idx >> 9, r = (idx >> 3) & 63, c = idx & 7;
            const __nv_bfloat16* src = (t == 0) ? Kh : (t == 1) ? Kl : (t == 2) ? Vh : Vl;
            cp_async16(stb + t * 8192 + toff128(r, c),
                       src + gofs + (size_t)r * KV_DIM + c * 8);
        }
    }
    CP_COMMIT();
    if (nkv > 1) {
        const uint32_t stb = sb + 16384 + 32768;
        const size_t gofs = (size_t)64 * KV_DIM + kvh * HEAD_DIM;
#pragma unroll
        for (int it = 0; it < 16; ++it) {
            const int idx = it * 128 + tid;
            const int t = idx >> 9, r = (idx >> 3) & 63, c = idx & 7;
            const __nv_bfloat16* src = (t == 0) ? Kh : (t == 1) ? Kl : (t == 2) ? Vh : Vl;
            cp_async16(stb + t * 8192 + toff128(r, c),
                       src + gofs + (size_t)r * KV_DIM + c * 8);
        }
        CP_COMMIT();
    }

    uint32_t qh[4][4], ql[4][4];
    float oacc[8][4];
#pragma unroll
    for (int nf = 0; nf < 8; ++nf)
#pragma unroll
        for (int q = 0; q < 4; ++q) oacc[nf][q] = 0.f;
    float m0 = -1e30f, m1 = -1e30f, l0 = 0.f, l1 = 0.f;

    for (int kt = 0; kt < nkv; ++kt) {
        if (kt + 1 < nkv) { CP_WAIT(1); } else { CP_WAIT(0); }
        __syncthreads();

        if (kt == 0) {
#pragma unroll
            for (int ks = 0; ks < 4; ++ks) {
                const uint32_t o = toff128(16 * wid + a_rofs, 2 * ks + a_cofs);
                ldsm_x4(qh[ks], sb + o);
                ldsm_x4(ql[ks], sb + 8192 + o);
            }
        }

        const uint32_t stb = sb + 16384 + (kt & 1) * 32768;

        float sc[8][4];
#pragma unroll
        for (int nf = 0; nf < 8; ++nf)
#pragma unroll
            for (int q = 0; q < 4; ++q) sc[nf][q] = 0.f;

#pragma unroll
        for (int ks = 0; ks < 4; ++ks) {
#pragma unroll
            for (int nb = 0; nb < 4; ++nb) {
                uint32_t khf[4], klf[4];
                const uint32_t o = toff128(16 * nb + b_rofs, 2 * ks + b_cofs);
                ldsm_x4(khf, stb + o);
                ldsm_x4(klf, stb + 8192 + o);
#pragma unroll
                for (int j = 0; j < 2; ++j) {
                    const int nf = 2 * nb + j;
                    const int h2 = j * 2;
                    mma16816(sc[nf], qh[ks], khf[h2], khf[h2 + 1]);
                    mma16816(sc[nf], qh[ks], klf[h2], klf[h2 + 1]);
                    mma16816(sc[nf], ql[ks], khf[h2], khf[h2 + 1]);
                }
            }
        }

        if (kt == bq) {
            const int rloc0 = 16 * wid + (lid >> 2);
#pragma unroll
            for (int nf = 0; nf < 8; ++nf) {
                const int cbase = nf * 8 + ((lid & 3) << 1);
#pragma unroll
                for (int q = 0; q < 4; ++q) {
                    const int col = cbase + (q & 1);
                    const int row = rloc0 + ((q >> 1) << 3);
                    if (col > row) sc[nf][q] = -1e30f;
                }
            }
        }

        float vx0 = -1e30f, vx1 = -1e30f;
#pragma unroll
        for (int nf = 0; nf < 8; ++nf) {
            vx0 = fmaxf(vx0, fmaxf(sc[nf][0], sc[nf][1]));
            vx1 = fmaxf(vx1, fmaxf(sc[nf][2], sc[nf][3]));
        }
        vx0 = fmaxf(vx0, __shfl_xor_sync(0xffffffffu, vx0, 1));
        vx0 = fmaxf(vx0, __shfl_xor_sync(0xffffffffu, vx0, 2));
        vx1 = fmaxf(vx1, __shfl_xor_sync(0xffffffffu, vx1, 1));
        vx1 = fmaxf(vx1, __shfl_xor_sync(0xffffffffu, vx1, 2));
        const float mn0 = fmaxf(m0, vx0);
        const float mn1 = fmaxf(m1, vx1);
        const float al0 = exp2f((m0 - mn0) * Cc);
        const float al1 = exp2f((m1 - mn1) * Cc);
        float sum0 = 0.f, sum1 = 0.f;
#pragma unroll
        for (int nf = 0; nf < 8; ++nf) {
            sc[nf][0] = exp2f((sc[nf][0] - mn0) * Cc);
            sc[nf][1] = exp2f((sc[nf][1] - mn0) * Cc);
            sc[nf][2] = exp2f((sc[nf][2] - mn1) * Cc);
            sc[nf][3] = exp2f((sc[nf][3] - mn1) * Cc);
            sum0 += sc[nf][0] + sc[nf][1];
            sum1 += sc[nf][2] + sc[nf][3];
        }
        sum0 += __shfl_xor_sync(0xffffffffu, sum0, 1);
        sum0 += __shfl_xor_sync(0xffffffffu, sum0, 2);
        sum1 += __shfl_xor_sync(0xffffffffu, sum1, 1);
        sum1 += __shfl_xor_sync(0xffffffffu, sum1, 2);
        l0 = l0 * al0 + sum0;
        l1 = l1 * al1 + sum1;
        m0 = mn0; m1 = mn1;
#pragma unroll
        for (int nf = 0; nf < 8; ++nf) {
            oacc[nf][0] *= al0; oacc[nf][1] *= al0;
            oacc[nf][2] *= al1; oacc[nf][3] *= al1;
        }

        uint32_t pah[4][4], pal[4][4];
#pragma unroll
        for (int ks = 0; ks < 4; ++ks) {
#pragma unroll
            for (int part = 0; part < 4; ++part) {
                const int nf = 2 * ks + (part >> 1);
                const int q0i = (part & 1) << 1;
                const float x = sc[nf][q0i], y = sc[nf][q0i + 1];
                const __nv_bfloat16 bx = __float2bfloat16(x);
                const __nv_bfloat16 by = __float2bfloat16(y);
                pah[ks][part] = pack_bf16(__bfloat162float(bx), __bfloat162float(by));
                pal[ks][part] = pack_bf16(x - __bfloat162float(bx),
                                          y - __bfloat162float(by));
            }
        }

#pragma unroll
        for (int ks = 0; ks < 4; ++ks) {
#pragma unroll
            for (int ng = 0; ng < 4; ++ng) {
                uint32_t vhf[4], vlf[4];
                const uint32_t o = toff128(16 * ks + a_rofs, 2 * ng + a_cofs);
                ldsm_x4_t(vhf, stb + 16384 + o);
                ldsm_x4_t(vlf, stb + 24576 + o);
#pragma unroll
                for (int j = 0; j < 2; ++j) {
                    const int nf = 2 * ng + j;
                    const int h2 = j * 2;
                    mma16816(oacc[nf], pah[ks], vhf[h2], vhf[h2 + 1]);
                    mma16816(oacc[nf], pah[ks], vlf[h2], vlf[h2 + 1]);
                    mma16816(oacc[nf], pal[ks], vhf[h2], vhf[h2 + 1]);
                }
            }
        }

        __syncthreads();
        if (kt + 2 < nkv) {
            const uint32_t nstb = sb + 16384 + (kt & 1) * 32768;
            const size_t gofs = (size_t)((kt + 2) * 64) * KV_DIM + kvh * HEAD_DIM;
#pragma unroll
            for (int it = 0; it < 16; ++it) {
                const int idx = it * 128 + tid;
                const int t = idx >> 9, r = (idx >> 3) & 63, c = idx & 7;
                const __nv_bfloat16* src = (t == 0) ? Kh : (t == 1) ? Kl : (t == 2) ? Vh : Vl;
                cp_async16(nstb + t * 8192 + toff128(r, c),
                           src + gofs + (size_t)r * KV_DIM + c * 8);
            }
            CP_COMMIT();
        }
    }

    const float il0 = 1.f / l0;
    const float il1 = 1.f / l1;
    const int row0 = q0 + 16 * wid + (lid >> 2);
    const size_t base0 = (size_t)row0 * D_MODEL + h * HEAD_DIM;
    const size_t base1 = base0 + (size_t)8 * D_MODEL;
#pragma unroll
    for (int nf = 0; nf < 8; ++nf) {
        const int cc = nf * 8 + ((lid & 3) << 1);
        const float a0 = oacc[nf][0] * il0, a1 = oacc[nf][1] * il0;
        const float b0 = oacc[nf][2] * il1, b1 = oacc[nf][3] * il1;
        const __nv_bfloat16 ha0 = __float2bfloat16(a0), ha1 = __float2bfloat16(a1);
        const __nv_bfloat16 hb0 = __float2bfloat16(b0), hb1 = __float2bfloat16(b1);
        *(uint32_t*)(Ohi + base0 + cc) = pack_bf16(__bfloat162float(ha0), __bfloat162float(ha1));
        *(uint32_t*)(Olo + base0 + cc) = pack_bf16(a0 - __bfloat162float(ha0),
                                                   a1 - __bfloat162float(ha1));
        *(uint32_t*)(Ohi + base1 + cc) = pack_bf16(__bfloat162float(hb0), __bfloat162float(hb1));
        *(uint32_t*)(Olo + base1 + cc) = pack_bf16(b0 - __bfloat162float(hb0),
                                                   b1 - __bfloat162float(hb1));
    }
}

// ---------------------------------------------------------------------------
// Launch
// ---------------------------------------------------------------------------
extern "C" void kernel_launch(void* const* d_in, const int* in_sizes, int n_in,
                              void* d_out, int out_size)
{
    const float* x     = (const float*)d_in[0];
    const float* Wq    = (const float*)d_in[1];
    const float* bq    = (const float*)d_in[2];
    const float* Wk    = (const float*)d_in[3];
    const float* bk    = (const float*)d_in[4];
    const float* Wv    = (const float*)d_in[5];
    const float* bv    = (const float*)d_in[6];
    const float* Wo    = (const float*)d_in[7];
    const float* bo    = (const float*)d_in[8];
    const float* freqs = (const float*)d_in[9];
    float* out = (float*)d_out;

    float *biasp;
    __nv_bfloat16 *ahi, *alo, *qhi, *qlo, *bhi, *blo, *khi, *klo, *vhi, *vlo;
    cudaGetSymbolAddress((void**)&biasp, g_bias);
    cudaGetSymbolAddress((void**)&ahi, s_ahi);
    cudaGetSymbolAddress((void**)&alo, s_alo);
    cudaGetSymbolAddress((void**)&qhi, s_qhi);
    cudaGetSymbolAddress((void**)&qlo, s_qlo);
    cudaGetSymbolAddress((void**)&bhi, s_bhi);
    cudaGetSymbolAddress((void**)&blo, s_blo);
    cudaGetSymbolAddress((void**)&khi, s_khi);
    cudaGetSymbolAddress((void**)&klo, s_klo);
    cudaGetSymbolAddress((void**)&vhi, s_vhi);
    cudaGetSymbolAddress((void**)&vlo, s_vlo);

    cudaFuncSetAttribute(gemm_tc_kernel, cudaFuncAttributeMaxDynamicSharedMemorySize,
                         GEMM_SMEM_BYTES);
    cudaFuncSetAttribute(attn_tc_kernel, cudaFuncAttributeMaxDynamicSharedMemorySize,
                         ATT_SMEM);

    const int n4x = (T_CTX * D_MODEL) / 4;

    // x -> bf16 hi/lo (A operand for QKV GEMM)
    cvt_hilo_kernel<<<(n4x + 255) / 256, 256>>>(x, ahi, alo, n4x);

    // Combined transposed weights [3072, 2048] and bias [3072]
    cvtT_kernel<<<dim3(D_MODEL / 32, D_MODEL / 32), 256>>>(Wq, bhi, blo, D_MODEL, D_MODEL, 0);
    cvtT_kernel<<<dim3(KV_DIM / 32, D_MODEL / 32), 256>>>(Wk, bhi, blo, D_MODEL, KV_DIM, D_MODEL);
    cvtT_kernel<<<dim3(KV_DIM / 32, D_MODEL / 32), 256>>>(Wv, bhi, blo, D_MODEL, KV_DIM, D_MODEL + KV_DIM);
    bias_concat_kernel<<<(QKV_N + 255) / 256, 256>>>(bq, bk, bv, biasp);

    // Fused QKV GEMM + bias + RoPE + hi/lo split epilogue
    gemm_tc_kernel<<<dim3(QKV_N / 128, T_CTX / 128), 256, GEMM_SMEM_BYTES>>>(
        ahi, alo, bhi, blo, biasp, nullptr, T_CTX, QKV_N, D_MODEL, 1,
        freqs, qhi, qlo, khi, klo, vhi, vlo);

    // Flash attention; epilogue writes O hi/lo into ahi/alo (x no longer needed)
    attn_tc_kernel<<<dim3(N_Q, T_CTX / 64), 128, ATT_SMEM>>>(
        qhi, qlo, khi, klo, vhi, vlo, ahi, alo);

    // Out projection
    cvtT_kernel<<<dim3(D_MODEL / 32, D_MODEL / 32), 256>>>(Wo, bhi, blo, D_MODEL, D_MODEL, 0);
    gemm_tc_kernel<<<dim3(D_MODEL / 128, T_CTX / 128), 256, GEMM_SMEM_BYTES>>>(
        ahi, alo, bhi, blo, bo, out, T_CTX, D_MODEL, D_MODEL, 0,
        nullptr, nullptr, nullptr, nullptr, nullptr, nullptr, nullptr);
}

// round 7
// speedup vs baseline: 4.3803x; 1.0981x over previous
#include <cuda_runtime.h>
#include <cuda_bf16.h>
#include <cstdint>

// Problem constants
#define T_CTX 2048
#define D_MODEL 2048
#define N_Q 32
#define N_KV 8
#define HEAD_DIM 64
#define KV_DIM (N_KV * HEAD_DIM)      // 512
#define QKV_N (D_MODEL + 2 * KV_DIM)  // 3072

// ---------------------------------------------------------------------------
// Scratch (allocation-free rule: __device__ globals)
// ---------------------------------------------------------------------------
__device__ __align__(16) float g_bias[QKV_N];
__device__ __align__(16) __nv_bfloat16 s_ahi[T_CTX * D_MODEL];   // x-split, then O
__device__ __align__(16) __nv_bfloat16 s_alo[T_CTX * D_MODEL];
__device__ __align__(16) __nv_bfloat16 s_qhi[T_CTX * D_MODEL];
__device__ __align__(16) __nv_bfloat16 s_qlo[T_CTX * D_MODEL];
__device__ __align__(16) __nv_bfloat16 s_bhi[QKV_N * D_MODEL];   // QKV W^T [N,K]
__device__ __align__(16) __nv_bfloat16 s_blo[QKV_N * D_MODEL];
__device__ __align__(16) __nv_bfloat16 s_whi[D_MODEL * D_MODEL]; // Wo^T
__device__ __align__(16) __nv_bfloat16 s_wlo[D_MODEL * D_MODEL];
__device__ __align__(16) __nv_bfloat16 s_khi[T_CTX * KV_DIM];
__device__ __align__(16) __nv_bfloat16 s_klo[T_CTX * KV_DIM];
__device__ __align__(16) __nv_bfloat16 s_vhi[T_CTX * KV_DIM];
__device__ __align__(16) __nv_bfloat16 s_vlo[T_CTX * KV_DIM];

// ---------------------------------------------------------------------------
// PTX helpers
// ---------------------------------------------------------------------------
__device__ __forceinline__ uint32_t smem_u32(const void* p) {
    uint32_t a;
    asm("{ .reg .u64 t; cvta.to.shared.u64 t, %1; cvt.u32.u64 %0, t; }"
        : "=r"(a) : "l"(p));
    return a;
}

__device__ __forceinline__ void cp_async16(uint32_t dst, const void* src) {
    asm volatile("cp.async.ca.shared.global [%0], [%1], 16;"
                 :: "r"(dst), "l"(src) : "memory");
}
#define CP_COMMIT() asm volatile("cp.async.commit_group;" ::: "memory")
#define CP_WAIT(n)  asm volatile("cp.async.wait_group %0;" :: "n"(n) : "memory")

__device__ __forceinline__ void ldsm_x4(uint32_t (&r)[4], uint32_t addr) {
    asm volatile("ldmatrix.sync.aligned.m8n8.x4.shared.b16 {%0,%1,%2,%3}, [%4];"
                 : "=r"(r[0]), "=r"(r[1]), "=r"(r[2]), "=r"(r[3]) : "r"(addr));
}

__device__ __forceinline__ void ldsm_x4_t(uint32_t (&r)[4], uint32_t addr) {
    asm volatile("ldmatrix.sync.aligned.m8n8.x4.trans.shared.b16 {%0,%1,%2,%3}, [%4];"
                 : "=r"(r[0]), "=r"(r[1]), "=r"(r[2]), "=r"(r[3]) : "r"(addr));
}

__device__ __forceinline__ void mma16816(float (&d)[4], const uint32_t (&a)[4],
                                         uint32_t b0, uint32_t b1) {
    asm volatile(
        "mma.sync.aligned.m16n8k16.row.col.f32.bf16.bf16.f32 "
        "{%0,%1,%2,%3}, {%4,%5,%6,%7}, {%8,%9}, {%0,%1,%2,%3};"
        : "+f"(d[0]), "+f"(d[1]), "+f"(d[2]), "+f"(d[3])
        : "r"(a[0]), "r"(a[1]), "r"(a[2]), "r"(a[3]), "r"(b0), "r"(b1));
}

__device__ __forceinline__ uint32_t pack_bf16(float x, float y) {
    __nv_bfloat162 t = __floats2bfloat162_rn(x, y);
    return *(uint32_t*)&t;
}

// GEMM smem tile: 128 rows x 32 bf16 (64B rows)
__device__ __forceinline__ uint32_t toff(int r, int c) {
    return (uint32_t)((r << 6) + ((c ^ ((r >> 1) & 3)) << 4));
}
// Attention smem tile: rows of 64 bf16 (128B, 8 chunks)
__device__ __forceinline__ uint32_t toff128(int r, int c) {
    return (uint32_t)((r << 7) + ((c ^ (r & 7)) << 4));
}

// ---------------------------------------------------------------------------
// bf16-split tensor-core GEMM, 4-stage cp.async pipeline, 1 barrier/iter.
// mode 0: C = fp32 out + bias.  mode 1: fused bias+RoPE+hi/lo split epilogue.
// ---------------------------------------------------------------------------
#define GEMM_STAGE_BYTES 32768
#define GEMM_SMEM_BYTES  (4 * GEMM_STAGE_BYTES)   // 128KB

__device__ __forceinline__ void stage_load(
    uint32_t stage_base,
    const __nv_bfloat16* __restrict__ Ah, const __nv_bfloat16* __restrict__ Al,
    const __nv_bfloat16* __restrict__ Bh, const __nv_bfloat16* __restrict__ Bl,
    int arow0, int brow0, int k0, int K, int tid)
{
    const __nv_bfloat16* srcs[4] = {Ah, Al, Bh, Bl};
#pragma unroll
    for (int t = 0; t < 4; ++t) {
        const __nv_bfloat16* src = srcs[t];
        const int grow0 = (t < 2) ? arow0 : brow0;
        const uint32_t tb = stage_base + t * 8192;
#pragma unroll
        for (int j = 0; j < 2; ++j) {
            const int idx = j * 256 + tid;
            const int r = idx >> 2;
            const int c = idx & 3;
            cp_async16(tb + toff(r, c),
                       src + (size_t)(grow0 + r) * K + k0 + c * 8);
        }
    }
}

__global__ __launch_bounds__(256, 1) void gemm_tc_kernel(
    const __nv_bfloat16* __restrict__ Ahi, const __nv_bfloat16* __restrict__ Alo,
    const __nv_bfloat16* __restrict__ Bhi, const __nv_bfloat16* __restrict__ Blo,
    const float* __restrict__ bias, float* __restrict__ C,
    int M, int N, int K, int mode,
    const float* __restrict__ freqs,
    __nv_bfloat16* __restrict__ qhi, __nv_bfloat16* __restrict__ qlo,
    __nv_bfloat16* __restrict__ khi, __nv_bfloat16* __restrict__ klo,
    __nv_bfloat16* __restrict__ vhi, __nv_bfloat16* __restrict__ vlo)
{
    extern __shared__ __align__(1024) char smem_raw[];
    const uint32_t sb = smem_u32(smem_raw);

    const int tid = threadIdx.x;
    const int wid = tid >> 5;
    const int lid = tid & 31;
    const int wm = wid & 1;
    const int wn = wid >> 1;
    const int arow0 = blockIdx.y * 128;
    const int brow0 = blockIdx.x * 128;

    float acc[4][4][4];
#pragma unroll
    for (int i = 0; i < 4; ++i)
#pragma unroll
        for (int j = 0; j < 4; ++j)
#pragma unroll
            for (int q = 0; q < 4; ++q) acc[i][j][q] = 0.f;

    const int NT = K >> 5;   // 64

    stage_load(sb,                        Ahi, Alo, Bhi, Blo, arow0, brow0, 0,  K, tid);
    CP_COMMIT();
    stage_load(sb + GEMM_STAGE_BYTES,     Ahi, Alo, Bhi, Blo, arow0, brow0, 32, K, tid);
    CP_COMMIT();
    stage_load(sb + 2 * GEMM_STAGE_BYTES, Ahi, Alo, Bhi, Blo, arow0, brow0, 64, K, tid);
    CP_COMMIT();

    const int sub = lid >> 3;
    const int l7  = lid & 7;
    const int a_rofs = ((sub & 1) << 3) + l7;
    const int a_cofs = (sub >> 1);
    const int b_rofs = ((sub >> 1) << 3) + l7;
    const int b_cofs = (sub & 1);

    for (int kt = 0; kt < NT; ++kt) {
        if (kt < NT - 2)       { CP_WAIT(2); }
        else if (kt == NT - 2) { CP_WAIT(1); }
        else                   { CP_WAIT(0); }
        __syncthreads();   // single barrier: loads visible + prior-iter reads done

        const uint32_t st = sb + (kt & 3) * GEMM_STAGE_BYTES;
        const uint32_t tAh = st, tAl = st + 8192, tBh = st + 16384, tBl = st + 24576;

#pragma unroll
        for (int ks = 0; ks < 2; ++ks) {
            const int kc = ks * 2;
            uint32_t ah[4][4], al[4][4];
#pragma unroll
            for (int ma = 0; ma < 4; ++ma) {
                const int row = wm * 64 + ma * 16 + a_rofs;
                const uint32_t o = toff(row, kc + a_cofs);
                ldsm_x4(ah[ma], tAh + o);
                ldsm_x4(al[ma], tAl + o);
            }
            uint32_t bh[2][4], bl[2][4];
#pragma unroll
            for (int nb = 0; nb < 2; ++nb) {
                const int row = wn * 32 + nb * 16 + b_rofs;
                const uint32_t o = toff(row, kc + b_cofs);
                ldsm_x4(bh[nb], tBh + o);
                ldsm_x4(bl[nb], tBl + o);
            }
#pragma unroll
            for (int ma = 0; ma < 4; ++ma) {
#pragma unroll
                for (int na = 0; na < 4; ++na) {
                    const int nb = na >> 1;
                    const int hi2 = (na & 1) << 1;
                    mma16816(acc[ma][na], ah[ma], bh[nb][hi2], bh[nb][hi2 + 1]);
                    mma16816(acc[ma][na], ah[ma], bl[nb][hi2], bl[nb][hi2 + 1]);
                    mma16816(acc[ma][na], al[ma], bh[nb][hi2], bh[nb][hi2 + 1]);
                }
            }
        }

        // prefetch kt+3 into slot (kt+3)&3 (= slot of kt-1, whose reads finished
        // before this iteration's top barrier) — WAR-safe without a 2nd barrier
        if (kt + 3 < NT) {
            stage_load(sb + ((kt + 3) & 3) * GEMM_STAGE_BYTES,
                       Ahi, Alo, Bhi, Blo, arow0, brow0, (kt + 3) << 5, K, tid);
            CP_COMMIT();
        }
    }

    const int er = lid >> 2;
    const int ec = (lid & 3) << 1;

    if (mode == 0) {
#pragma unroll
        for (int ma = 0; ma < 4; ++ma) {
            const int row = arow0 + wm * 64 + ma * 16 + er;
#pragma unroll
            for (int na = 0; na < 4; ++na) {
                const int col = brow0 + wn * 32 + na * 8 + ec;
                const float b0 = bias[col], b1 = bias[col + 1];
                float2 v0 = make_float2(acc[ma][na][0] + b0, acc[ma][na][1] + b1);
                float2 v1 = make_float2(acc[ma][na][2] + b0, acc[ma][na][3] + b1);
                *(float2*)(C + (size_t)row * N + col) = v0;
                *(float2*)(C + (size_t)(row + 8) * N + col) = v1;
            }
        }
        return;
    }

    // ---- mode 1: fused bias + RoPE + hi/lo split epilogue ----
    __syncthreads();   // all mainloop smem reads done before reuse
    float* cs = (float*)smem_raw;
#pragma unroll
    for (int ma = 0; ma < 4; ++ma) {
        const int rl0 = wm * 64 + ma * 16 + er;
#pragma unroll
        for (int na = 0; na < 4; ++na) {
            const int cl = wn * 32 + na * 8 + ec;
            const float b0 = bias[brow0 + cl], b1 = bias[brow0 + cl + 1];
            cs[rl0 * 132 + cl]             = acc[ma][na][0] + b0;
            cs[rl0 * 132 + cl + 1]         = acc[ma][na][1] + b1;
            cs[(rl0 + 8) * 132 + cl]       = acc[ma][na][2] + b0;
            cs[(rl0 + 8) * 132 + cl + 1]   = acc[ma][na][3] + b1;
        }
    }
    __syncthreads();

    if (brow0 < D_MODEL + KV_DIM) {
        const bool isq = (brow0 < D_MODEL);
        __nv_bfloat16* hi = isq ? qhi : khi;
        __nv_bfloat16* lo = isq ? qlo : klo;
        const int ld = isq ? D_MODEL : KV_DIM;
        const int colbase = isq ? brow0 : (brow0 - D_MODEL);
#pragma unroll
        for (int p = tid; p < 128 * 64; p += 256) {
            const int r  = p >> 6;
            const int pc = p & 63;
            const int h2 = pc >> 5;
            const int d  = pc & 31;
            const int c1 = (h2 << 6) + d;
            const float x1 = cs[r * 132 + c1];
            const float x2 = cs[r * 132 + c1 + 32];
            const int t = arow0 + r;
            const float f = freqs[t * 32 + d];
            float sn, csn;
            __sincosf(f, &sn, &csn);
            const float r1 = x1 * csn - x2 * sn;
            const float r2 = x1 * sn + x2 * csn;
            const __nv_bfloat16 h1 = __float2bfloat16(r1);
            const __nv_bfloat16 h2b = __float2bfloat16(r2);
            const size_t o1 = (size_t)t * ld + colbase + c1;
            hi[o1]      = h1;
            hi[o1 + 32] = h2b;
            lo[o1]      = __float2bfloat16(r1 - __bfloat162float(h1));
            lo[o1 + 32] = __float2bfloat16(r2 - __bfloat162float(h2b));
        }
    } else {
        const int colbase = brow0 - (D_MODEL + KV_DIM);
#pragma unroll
        for (int p = tid; p < 128 * 64; p += 256) {
            const int r = p >> 6;
            const int c = (p & 63) << 1;
            const float x0 = cs[r * 132 + c];
            const float x1 = cs[r * 132 + c + 1];
            const __nv_bfloat16 h0 = __float2bfloat16(x0);
            const __nv_bfloat16 h1 = __float2bfloat16(x1);
            const size_t o = (size_t)(arow0 + r) * KV_DIM + colbase + c;
            *(uint32_t*)(vhi + o) = pack_bf16(__bfloat162float(h0), __bfloat162float(h1));
            *(uint32_t*)(vlo + o) = pack_bf16(x0 - __bfloat162float(h0),
                                              x1 - __bfloat162float(h1));
        }
    }
}

// ---------------------------------------------------------------------------
// fp32 -> bf16 hi/lo split (for x)
// ---------------------------------------------------------------------------
__global__ void cvt_hilo_kernel(const float* __restrict__ in,
                                __nv_bfloat16* __restrict__ hi,
                                __nv_bfloat16* __restrict__ lo, int n4)
{
    int i = blockIdx.x * blockDim.x + threadIdx.x;
    if (i >= n4) return;
    float4 v = ((const float4*)in)[i];
    __nv_bfloat16 h0 = __float2bfloat16(v.x);
    __nv_bfloat16 h1 = __float2bfloat16(v.y);
    __nv_bfloat16 h2 = __float2bfloat16(v.z);
    __nv_bfloat16 h3 = __float2bfloat16(v.w);
    uint2 ph, pl;
    ph.x = pack_bf16(__bfloat162float(h0), __bfloat162float(h1));
    ph.y = pack_bf16(__bfloat162float(h2), __bfloat162float(h3));
    pl.x = pack_bf16(v.x - __bfloat162float(h0), v.y - __bfloat162float(h1));
    pl.y = pack_bf16(v.z - __bfloat162float(h2), v.w - __bfloat162float(h3));
    ((uint2*)hi)[i] = ph;
    ((uint2*)lo)[i] = pl;
}

// ---------------------------------------------------------------------------
// All-weights transpose + split, one launch. z: 0=Wq 1=Wk 2=Wv 3=Wo.
// Vectorized uint32 (2xbf16) stores.
// ---------------------------------------------------------------------------
__global__ __launch_bounds__(256) void cvtW_all_kernel(
    const float* __restrict__ Wq, const float* __restrict__ Wk,
    const float* __restrict__ Wv, const float* __restrict__ Wo,
    __nv_bfloat16* __restrict__ bhi, __nv_bfloat16* __restrict__ blo,
    __nv_bfloat16* __restrict__ whi, __nv_bfloat16* __restrict__ wlo)
{
    const int z = blockIdx.z;
    const float* W;
    int N, rowOfs;
    __nv_bfloat16 *hi, *lo;
    if (z == 0)      { W = Wq; N = D_MODEL; rowOfs = 0;                 hi = bhi; lo = blo; }
    else if (z == 1) { W = Wk; N = KV_DIM;  rowOfs = D_MODEL;           hi = bhi; lo = blo; }
    else if (z == 2) { W = Wv; N = KV_DIM;  rowOfs = D_MODEL + KV_DIM;  hi = bhi; lo = blo; }
    else             { W = Wo; N = D_MODEL; rowOfs = 0;                 hi = whi; lo = wlo; }

    const int nb = blockIdx.x * 32;
    if (nb >= N) return;
    const int kb = blockIdx.y * 32;

    __shared__ float t[32][33];
    const int tx = threadIdx.x & 31, ty = threadIdx.x >> 5;
#pragma unroll
    for (int i = 0; i < 32; i += 8)
        t[ty + i][tx] = W[(size_t)(kb + ty + i) * N + nb + tx];
    __syncthreads();

#pragma unroll
    for (int j = 0; j < 2; ++j) {
        const int idx = threadIdx.x + j * 256;
        const int nl = idx >> 4;
        const int kp = idx & 15;
        const float v0 = t[2 * kp][nl];
        const float v1 = t[2 * kp + 1][nl];
        const __nv_bfloat16 h0 = __float2bfloat16(v0);
        const __nv_bfloat16 h1 = __float2bfloat16(v1);
        const size_t o = (size_t)(rowOfs + nb + nl) * D_MODEL + kb + 2 * kp;
        *(uint32_t*)(hi + o) = pack_bf16(__bfloat162float(h0), __bfloat162float(h1));
        *(uint32_t*)(lo + o) = pack_bf16(v0 - __bfloat162float(h0),
                                         v1 - __bfloat162float(h1));
    }
}

// ---------------------------------------------------------------------------
// Bias concat: [bq | bk | bv]
// ---------------------------------------------------------------------------
__global__ void bias_concat_kernel(const float* __restrict__ bq,
                                   const float* __restrict__ bk,
                                   const float* __restrict__ bv,
                                   float* __restrict__ dst)
{
    int i = blockIdx.x * blockDim.x + threadIdx.x;
    if (i >= QKV_N) return;
    float v;
    if (i < D_MODEL) v = bq[i];
    else if (i < D_MODEL + KV_DIM) v = bk[i - D_MODEL];
    else v = bv[i - D_MODEL - KV_DIM];
    dst[i] = v;
}

// ---------------------------------------------------------------------------
// Tensor-core flash attention (causal, GQA), bf16 hi/lo split.
// 3-stage KV pipeline, 1 barrier/iter. smem: Q 16KB + 3x32KB = 112KB.
// ---------------------------------------------------------------------------
#define ATT_SMEM (16384 + 3 * 32768)

__global__ __launch_bounds__(128, 2) void attn_tc_kernel(
    const __nv_bfloat16* __restrict__ Qh, const __nv_bfloat16* __restrict__ Ql,
    const __nv_bfloat16* __restrict__ Kh, const __nv_bfloat16* __restrict__ Kl,
    const __nv_bfloat16* __restrict__ Vh, const __nv_bfloat16* __restrict__ Vl,
    __nv_bfloat16* __restrict__ Ohi, __nv_bfloat16* __restrict__ Olo)
{
    extern __shared__ __align__(1024) char smem_raw[];
    const uint32_t sb = smem_u32(smem_raw);
    const int tid = threadIdx.x;
    const int wid = tid >> 5;
    const int lid = tid & 31;
    const int h   = blockIdx.x;
    const int bq  = (int)(gridDim.y - 1 - blockIdx.y);
    const int q0  = bq * 64;
    const int kvh = h >> 2;
    const int nkv = bq + 1;
    const float Cc = 0.125f * 1.44269504088896f;

    const int sub = lid >> 3;
    const int l7  = lid & 7;
    const int a_rofs = ((sub & 1) << 3) + l7;
    const int a_cofs = (sub >> 1);
    const int b_rofs = ((sub >> 1) << 3) + l7;
    const int b_cofs = (sub & 1);

    // group 0: Q tiles + KV stage 0
#pragma unroll
    for (int it = 0; it < 8; ++it) {
        const int idx = it * 128 + tid;
        const int t = idx >> 9, r = (idx >> 3) & 63, c = idx & 7;
        const __nv_bfloat16* src = t ? Ql : Qh;
        cp_async16(sb + t * 8192 + toff128(r, c),
                   src + (size_t)(q0 + r) * D_MODEL + h * HEAD_DIM + c * 8);
    }
    {
        const uint32_t stb = sb + 16384;
        const size_t gofs = (size_t)kvh * HEAD_DIM;
#pragma unroll
        for (int it = 0; it < 16; ++it) {
            const int idx = it * 128 + tid;
            const int t = idx >> 9, r = (idx >> 3) & 63, c = idx & 7;
            const __nv_bfloat16* src = (t == 0) ? Kh : (t == 1) ? Kl : (t == 2) ? Vh : Vl;
            cp_async16(stb + t * 8192 + toff128(r, c),
                       src + gofs + (size_t)r * KV_DIM + c * 8);
        }
    }
    CP_COMMIT();
    if (nkv > 1) {
        const uint32_t stb = sb + 16384 + 32768;
        const size_t gofs = (size_t)64 * KV_DIM + kvh * HEAD_DIM;
#pragma unroll
        for (int it = 0; it < 16; ++it) {
            const int idx = it * 128 + tid;
            const int t = idx >> 9, r = (idx >> 3) & 63, c = idx & 7;
            const __nv_bfloat16* src = (t == 0) ? Kh : (t == 1) ? Kl : (t == 2) ? Vh : Vl;
            cp_async16(stb + t * 8192 + toff128(r, c),
                       src + gofs + (size_t)r * KV_DIM + c * 8);
        }
        CP_COMMIT();
    }

    uint32_t qh[4][4], ql[4][4];
    float oacc[8][4];
#pragma unroll
    for (int nf = 0; nf < 8; ++nf)
#pragma unroll
        for (int q = 0; q < 4; ++q) oacc[nf][q] = 0.f;
    float m0 = -1e30f, m1 = -1e30f, l0 = 0.f, l1 = 0.f;

    int slot = 0;
    for (int kt = 0; kt < nkv; ++kt) {
        if (kt + 1 < nkv) { CP_WAIT(1); } else { CP_WAIT(0); }
        __syncthreads();   // single barrier per iteration

        if (kt == 0) {
#pragma unroll
            for (int ks = 0; ks < 4; ++ks) {
                const uint32_t o = toff128(16 * wid + a_rofs, 2 * ks + a_cofs);
                ldsm_x4(qh[ks], sb + o);
                ldsm_x4(ql[ks], sb + 8192 + o);
            }
        }

        const uint32_t stb = sb + 16384 + slot * 32768;

        float sc[8][4];
#pragma unroll
        for (int nf = 0; nf < 8; ++nf)
#pragma unroll
            for (int q = 0; q < 4; ++q) sc[nf][q] = 0.f;

#pragma unroll
        for (int ks = 0; ks < 4; ++ks) {
#pragma unroll
            for (int nb = 0; nb < 4; ++nb) {
                uint32_t khf[4], klf[4];
                const uint32_t o = toff128(16 * nb + b_rofs, 2 * ks + b_cofs);
                ldsm_x4(khf, stb + o);
                ldsm_x4(klf, stb + 8192 + o);
#pragma unroll
                for (int j = 0; j < 2; ++j) {
                    const int nf = 2 * nb + j;
                    const int h2 = j * 2;
                    mma16816(sc[nf], qh[ks], khf[h2], khf[h2 + 1]);
                    mma16816(sc[nf], qh[ks], klf[h2], klf[h2 + 1]);
                    mma16816(sc[nf], ql[ks], khf[h2], khf[h2 + 1]);
                }
            }
        }

        if (kt == bq) {
            const int rloc0 = 16 * wid + (lid >> 2);
#pragma unroll
            for (int nf = 0; nf < 8; ++nf) {
                const int cbase = nf * 8 + ((lid & 3) << 1);
#pragma unroll
                for (int q = 0; q < 4; ++q) {
                    const int col = cbase + (q & 1);
                    const int row = rloc0 + ((q >> 1) << 3);
                    if (col > row) sc[nf][q] = -1e30f;
                }
            }
        }

        float vx0 = -1e30f, vx1 = -1e30f;
#pragma unroll
        for (int nf = 0; nf < 8; ++nf) {
            vx0 = fmaxf(vx0, fmaxf(sc[nf][0], sc[nf][1]));
            vx1 = fmaxf(vx1, fmaxf(sc[nf][2], sc[nf][3]));
        }
        vx0 = fmaxf(vx0, __shfl_xor_sync(0xffffffffu, vx0, 1));
        vx0 = fmaxf(vx0, __shfl_xor_sync(0xffffffffu, vx0, 2));
        vx1 = fmaxf(vx1, __shfl_xor_sync(0xffffffffu, vx1, 1));
        vx1 = fmaxf(vx1, __shfl_xor_sync(0xffffffffu, vx1, 2));
        const float mn0 = fmaxf(m0, vx0);
        const float mn1 = fmaxf(m1, vx1);
        const float al0 = exp2f((m0 - mn0) * Cc);
        const float al1 = exp2f((m1 - mn1) * Cc);
        float sum0 = 0.f, sum1 = 0.f;
#pragma unroll
        for (int nf = 0; nf < 8; ++nf) {
            sc[nf][0] = exp2f((sc[nf][0] - mn0) * Cc);
            sc[nf][1] = exp2f((sc[nf][1] - mn0) * Cc);
            sc[nf][2] = exp2f((sc[nf][2] - mn1) * Cc);
            sc[nf][3] = exp2f((sc[nf][3] - mn1) * Cc);
            sum0 += sc[nf][0] + sc[nf][1];
            sum1 += sc[nf][2] + sc[nf][3];
        }
        sum0 += __shfl_xor_sync(0xffffffffu, sum0, 1);
        sum0 += __shfl_xor_sync(0xffffffffu, sum0, 2);
        sum1 += __shfl_xor_sync(0xffffffffu, sum1, 1);
        sum1 += __shfl_xor_sync(0xffffffffu, sum1, 2);
        l0 = l0 * al0 + sum0;
        l1 = l1 * al1 + sum1;
        m0 = mn0; m1 = mn1;
#pragma unroll
        for (int nf = 0; nf < 8; ++nf) {
            oacc[nf][0] *= al0; oacc[nf][1] *= al0;
            oacc[nf][2] *= al1; oacc[nf][3] *= al1;
        }

        uint32_t pah[4][4], pal[4][4];
#pragma unroll
        for (int ks = 0; ks < 4; ++ks) {
#pragma unroll
            for (int part = 0; part < 4; ++part) {
                const int nf = 2 * ks + (part >> 1);
                const int q0i = (part & 1) << 1;
                const float x = sc[nf][q0i], y = sc[nf][q0i + 1];
                const __nv_bfloat16 bx = __float2bfloat16(x);
                const __nv_bfloat16 by = __float2bfloat16(y);
                pah[ks][part] = pack_bf16(__bfloat162float(bx), __bfloat162float(by));
                pal[ks][part] = pack_bf16(x - __bfloat162float(bx),
                                          y - __bfloat162float(by));
            }
        }

#pragma unroll
        for (int ks = 0; ks < 4; ++ks) {
#pragma unroll
            for (int ng = 0; ng < 4; ++ng) {
                uint32_t vhf[4], vlf[4];
                const uint32_t o = toff128(16 * ks + a_rofs, 2 * ng + a_cofs);
                ldsm_x4_t(vhf, stb + 16384 + o);
                ldsm_x4_t(vlf, stb + 24576 + o);
#pragma unroll
                for (int j = 0; j < 2; ++j) {
                    const int nf = 2 * ng + j;
                    const int h2 = j * 2;
                    mma16816(oacc[nf], pah[ks], vhf[h2], vhf[h2 + 1]);
                    mma16816(oacc[nf], pah[ks], vlf[h2], vlf[h2 + 1]);
                    mma16816(oacc[nf], pal[ks], vhf[h2], vhf[h2 + 1]);
                }
            }
        }

        // prefetch kt+2 into slot (kt+2)%3 (= slot of kt-1; reads done pre-barrier)
        if (kt + 2 < nkv) {
            const int ns = (slot + 2 >= 3) ? (slot + 2 - 3) : (slot + 2);
            const uint32_t nstb = sb + 16384 + ns * 32768;
            const size_t gofs = (size_t)((kt + 2) * 64) * KV_DIM + kvh * HEAD_DIM;
#pragma unroll
            for (int it = 0; it < 16; ++it) {
                const int idx = it * 128 + tid;
                const int t = idx >> 9, r = (idx >> 3) & 63, c = idx & 7;
                const __nv_bfloat16* src = (t == 0) ? Kh : (t == 1) ? Kl : (t == 2) ? Vh : Vl;
                cp_async16(nstb + t * 8192 + toff128(r, c),
                           src + gofs + (size_t)r * KV_DIM + c * 8);
            }
            CP_COMMIT();
        }
        slot = (slot == 2) ? 0 : slot + 1;
    }

    const float il0 = 1.f / l0;
    const float il1 = 1.f / l1;
    const int row0 = q0 + 16 * wid + (lid >> 2);
    const size_t base0 = (size_t)row0 * D_MODEL + h * HEAD_DIM;
    const size_t base1 = base0 + (size_t)8 * D_MODEL;
#pragma unroll
    for (int nf = 0; nf < 8; ++nf) {
        const int cc = nf * 8 + ((lid & 3) << 1);
        const float a0 = oacc[nf][0] * il0, a1 = oacc[nf][1] * il0;
        const float b0 = oacc[nf][2] * il1, b1 = oacc[nf][3] * il1;
        const __nv_bfloat16 ha0 = __float2bfloat16(a0), ha1 = __float2bfloat16(a1);
        const __nv_bfloat16 hb0 = __float2bfloat16(b0), hb1 = __float2bfloat16(b1);
        *(uint32_t*)(Ohi + base0 + cc) = pack_bf16(__bfloat162float(ha0), __bfloat162float(ha1));
        *(uint32_t*)(Olo + base0 + cc) = pack_bf16(a0 - __bfloat162float(ha0),
                                                   a1 - __bfloat162float(ha1));
        *(uint32_t*)(Ohi + base1 + cc) = pack_bf16(__bfloat162float(hb0), __bfloat162float(hb1));
        *(uint32_t*)(Olo + base1 + cc) = pack_bf16(b0 - __bfloat162float(hb0),
                                                   b1 - __bfloat162float(hb1));
    }
}

// ---------------------------------------------------------------------------
// Launch
// ---------------------------------------------------------------------------
extern "C" void kernel_launch(void* const* d_in, const int* in_sizes, int n_in,
                              void* d_out, int out_size)
{
    const float* x     = (const float*)d_in[0];
    const float* Wq    = (const float*)d_in[1];
    const float* bq    = (const float*)d_in[2];
    const float* Wk    = (const float*)d_in[3];
    const float* bk    = (const float*)d_in[4];
    const float* Wv    = (const float*)d_in[5];
    const float* bv    = (const float*)d_in[6];
    const float* Wo    = (const float*)d_in[7];
    const float* bo    = (const float*)d_in[8];
    const float* freqs = (const float*)d_in[9];
    float* out = (float*)d_out;

    float *biasp;
    __nv_bfloat16 *ahi, *alo, *qhi, *qlo, *bhi, *blo, *whi, *wlo, *khi, *klo, *vhi, *vlo;
    cudaGetSymbolAddress((void**)&biasp, g_bias);
    cudaGetSymbolAddress((void**)&ahi, s_ahi);
    cudaGetSymbolAddress((void**)&alo, s_alo);
    cudaGetSymbolAddress((void**)&qhi, s_qhi);
    cudaGetSymbolAddress((void**)&qlo, s_qlo);
    cudaGetSymbolAddress((void**)&bhi, s_bhi);
    cudaGetSymbolAddress((void**)&blo, s_blo);
    cudaGetSymbolAddress((void**)&whi, s_whi);
    cudaGetSymbolAddress((void**)&wlo, s_wlo);
    cudaGetSymbolAddress((void**)&khi, s_khi);
    cudaGetSymbolAddress((void**)&klo, s_klo);
    cudaGetSymbolAddress((void**)&vhi, s_vhi);
    cudaGetSymbolAddress((void**)&vlo, s_vlo);

    cudaFuncSetAttribute(gemm_tc_kernel, cudaFuncAttributeMaxDynamicSharedMemorySize,
                         GEMM_SMEM_BYTES);
    cudaFuncSetAttribute(attn_tc_kernel, cudaFuncAttributeMaxDynamicSharedMemorySize,
                         ATT_SMEM);

    const int n4x = (T_CTX * D_MODEL) / 4;

    // 0: all weight conversions in one launch (Wo up-front into its own buffers)
    cvtW_all_kernel<<<dim3(64, 64, 4), 256>>>(Wq, Wk, Wv, Wo, bhi, blo, whi, wlo);
    // 1: bias concat
    bias_concat_kernel<<<(QKV_N + 255) / 256, 256>>>(bq, bk, bv, biasp);
    // 2: x -> bf16 hi/lo
    cvt_hilo_kernel<<<(n4x + 255) / 256, 256>>>(x, ahi, alo, n4x);

    // 3: fused QKV GEMM + bias + RoPE + hi/lo split epilogue
    gemm_tc_kernel<<<dim3(QKV_N / 128, T_CTX / 128), 256, GEMM_SMEM_BYTES>>>(
        ahi, alo, bhi, blo, biasp, nullptr, T_CTX, QKV_N, D_MODEL, 1,
        freqs, qhi, qlo, khi, klo, vhi, vlo);

    // 4: flash attention; O hi/lo into ahi/alo
    attn_tc_kernel<<<dim3(N_Q, T_CTX / 64), 128, ATT_SMEM>>>(
        qhi, qlo, khi, klo, vhi, vlo, ahi, alo);

    // 5: out projection
    gemm_tc_kernel<<<dim3(D_MODEL / 128, T_CTX / 128), 256, GEMM_SMEM_BYTES>>>(
        ahi, alo, whi, wlo, bo, out, T_CTX, D_MODEL, D_MODEL, 0,
        nullptr, nullptr, nullptr, nullptr, nullptr, nullptr, nullptr);
}